// round 1
// baseline (speedup 1.0000x reference)
#include <cuda_runtime.h>
#include <math.h>

// ---------------- problem constants ----------------
#define BATCH    2
#define LQ       21760            // 128^2+64^2+32^2+16^2
#define LEN_IN   21760
#define DMODEL   256
#define NHEADS   8
#define NLEV     4
#define NPTS     4
#define HDIM     32
#define MROWS    (BATCH*LQ)       // 43520

// level geometry
__device__ __constant__ int c_lvlH[4]    = {128, 64, 32, 16};
__device__ __constant__ int c_lvlW[4]    = {128, 64, 32, 16};
__device__ __constant__ int c_lvlBase[4] = {0, 16384, 20480, 21504};

// ---------------- scratch (device globals; no allocation allowed) ----------------
__device__ float g_value[(size_t)BATCH*LEN_IN*DMODEL];   // value projection
__device__ float g_off  [(size_t)MROWS*256];             // sampling offsets (raw)
__device__ float g_attnl[(size_t)MROWS*128];             // attention logits (pre-softmax)
__device__ float g_samp [(size_t)MROWS*DMODEL];          // deformable-sampled output

// ---------------- generic SGEMM: C[M,N] = A[M,K] * W[K,N] + bias[N] ----------------
// Requirements: M%128==0, N%128==0, K%16==0 (true for all 4 uses).
#define BM 128
#define BN 128
#define BK 16
#define TM 8
#define TN 8

__global__ __launch_bounds__(256, 2)
void sgemm_bias(const float* __restrict__ A, const float* __restrict__ W,
                const float* __restrict__ bias, float* __restrict__ C,
                int M, int N, int K)
{
    __shared__ float As[BK][BM];
    __shared__ float Bs[BK][BN];

    const int tid  = threadIdx.x;
    const int bm   = blockIdx.y * BM;
    const int bn   = blockIdx.x * BN;
    const int tcol = tid % (BN / TN);   // 0..15
    const int trow = tid / (BN / TN);   // 0..15

    float acc[TM][TN];
    #pragma unroll
    for (int i = 0; i < TM; i++)
        #pragma unroll
        for (int j = 0; j < TN; j++) acc[i][j] = 0.f;

    for (int k0 = 0; k0 < K; k0 += BK) {
        // load A tile (BM x BK) -> As transposed [BK][BM]
        #pragma unroll
        for (int t = 0; t < 2; t++) {
            int i   = tid + t * 256;       // 0..511 (float4 index)
            int row = i >> 2;              // 0..127
            int c4  = i & 3;               // 0..3
            float4 v = *(const float4*)(A + (size_t)(bm + row) * K + k0 + c4 * 4);
            As[c4 * 4 + 0][row] = v.x;
            As[c4 * 4 + 1][row] = v.y;
            As[c4 * 4 + 2][row] = v.z;
            As[c4 * 4 + 3][row] = v.w;
        }
        // load W tile (BK x BN) -> Bs row-major
        #pragma unroll
        for (int t = 0; t < 2; t++) {
            int i   = tid + t * 256;       // 0..511
            int row = i >> 5;              // 0..15
            int c4  = i & 31;              // 0..31
            float4 v = *(const float4*)(W + (size_t)(k0 + row) * N + bn + c4 * 4);
            *(float4*)&Bs[row][c4 * 4] = v;
        }
        __syncthreads();

        #pragma unroll
        for (int k = 0; k < BK; k++) {
            float a[TM], b[TN];
            #pragma unroll
            for (int i = 0; i < TM; i += 4)
                *(float4*)&a[i] = *(const float4*)&As[k][trow * TM + i];
            #pragma unroll
            for (int j = 0; j < TN; j += 4)
                *(float4*)&b[j] = *(const float4*)&Bs[k][tcol * TN + j];
            #pragma unroll
            for (int i = 0; i < TM; i++)
                #pragma unroll
                for (int j = 0; j < TN; j++)
                    acc[i][j] = fmaf(a[i], b[j], acc[i][j]);
        }
        __syncthreads();
    }

    // epilogue: bias add, float4 stores
    #pragma unroll
    for (int i = 0; i < TM; i++) {
        int r = bm + trow * TM + i;
        #pragma unroll
        for (int j = 0; j < TN; j += 4) {
            int c = bn + tcol * TN + j;
            float4 bv = *(const float4*)(bias + c);
            float4 v;
            v.x = acc[i][j + 0] + bv.x;
            v.y = acc[i][j + 1] + bv.y;
            v.z = acc[i][j + 2] + bv.z;
            v.w = acc[i][j + 3] + bv.w;
            *(float4*)(C + (size_t)r * N + c) = v;
        }
    }
}

// ---------------- fused softmax + deformable bilinear sampling ----------------
// One warp per (b, q, head). lane = head-dim channel (0..31) so every corner
// gather is a coalesced 128B line from g_value.
__global__ __launch_bounds__(256)
void deform_sample(const float* __restrict__ refp)
{
    const int warp = (blockIdx.x * blockDim.x + threadIdx.x) >> 5;
    const int lane = threadIdx.x & 31;
    const int total = MROWS * NHEADS;
    if (warp >= total) return;

    const int h  = warp & 7;
    const int bq = warp >> 3;                    // b*LQ + q
    const int b  = bq / LQ;

    // ---- softmax over 16 attention logits for this (b,q,h) ----
    const float* al = g_attnl + (size_t)bq * 128 + h * 16;
    float logit = (lane < 16) ? al[lane] : -INFINITY;
    float mx = logit;
    #pragma unroll
    for (int s = 16; s; s >>= 1) mx = fmaxf(mx, __shfl_xor_sync(0xffffffffu, mx, s));
    float e = (lane < 16) ? __expf(logit - mx) : 0.f;
    float sum = e;
    #pragma unroll
    for (int s = 16; s; s >>= 1) sum += __shfl_xor_sync(0xffffffffu, sum, s);
    const float watt = e / sum;                  // lane p (<16): weight of point p

    // ---- per-lane staged data: 32 offset floats, 8 ref floats ----
    const float offv = g_off[(size_t)bq * 256 + h * 32 + lane];
    const float refv = (lane < 8) ? refp[(size_t)bq * 8 + lane] : 0.f;

    const float* vbase = g_value + ((size_t)b * LEN_IN) * DMODEL + h * HDIM + lane;

    float acc = 0.f;
    #pragma unroll
    for (int p = 0; p < 16; p++) {
        const int l = p >> 2;
        const float aw = __shfl_sync(0xffffffffu, watt, p);
        const float ox = __shfl_sync(0xffffffffu, offv, 2 * p);
        const float oy = __shfl_sync(0xffffffffu, offv, 2 * p + 1);
        const float rx = __shfl_sync(0xffffffffu, refv, 2 * l);
        const float ry = __shfl_sync(0xffffffffu, refv, 2 * l + 1);

        const int Wl = c_lvlW[l], Hl = c_lvlH[l];
        const int base = c_lvlBase[l];

        // loc = ref + off/normalizer;  ix = loc*W - 0.5
        const float ix = fmaf(rx, (float)Wl, ox) - 0.5f;
        const float iy = fmaf(ry, (float)Hl, oy) - 0.5f;
        const float x0f = floorf(ix), y0f = floorf(iy);
        const int x0 = (int)x0f, y0 = (int)y0f;
        const float fx = ix - x0f, fy = iy - y0f;

        const bool vx0 = (x0 >= 0) && (x0 < Wl);
        const bool vx1 = (x0 + 1 >= 0) && (x0 + 1 < Wl);
        const bool vy0 = (y0 >= 0) && (y0 < Hl);
        const bool vy1 = (y0 + 1 >= 0) && (y0 + 1 < Hl);

        const float w00 = (1.f - fx) * (1.f - fy) * aw;
        const float w01 = fx * (1.f - fy) * aw;
        const float w10 = (1.f - fx) * fy * aw;
        const float w11 = fx * fy * aw;

        if (vy0 && vx0) acc = fmaf(w00, __ldg(vbase + (size_t)(base + y0 * Wl + x0) * DMODEL), acc);
        if (vy0 && vx1) acc = fmaf(w01, __ldg(vbase + (size_t)(base + y0 * Wl + x0 + 1) * DMODEL), acc);
        if (vy1 && vx0) acc = fmaf(w10, __ldg(vbase + (size_t)(base + (y0 + 1) * Wl + x0) * DMODEL), acc);
        if (vy1 && vx1) acc = fmaf(w11, __ldg(vbase + (size_t)(base + (y0 + 1) * Wl + x0 + 1) * DMODEL), acc);
    }

    g_samp[(size_t)bq * DMODEL + h * HDIM + lane] = acc;
}

// ---------------- launch ----------------
extern "C" void kernel_launch(void* const* d_in, const int* in_sizes, int n_in,
                              void* d_out, int out_size)
{
    (void)in_sizes; (void)n_in; (void)out_size;
    const float* query  = (const float*)d_in[0];
    const float* refp   = (const float*)d_in[1];
    const float* xin    = (const float*)d_in[2];
    const float* W_off  = (const float*)d_in[3];
    const float* b_off  = (const float*)d_in[4];
    const float* W_attn = (const float*)d_in[5];
    const float* b_attn = (const float*)d_in[6];
    const float* W_val  = (const float*)d_in[7];
    const float* b_val  = (const float*)d_in[8];
    const float* W_out  = (const float*)d_in[9];
    const float* b_out  = (const float*)d_in[10];
    float* out = (float*)d_out;

    float *p_value, *p_off, *p_attnl, *p_samp;
    cudaGetSymbolAddress((void**)&p_value, g_value);
    cudaGetSymbolAddress((void**)&p_off,   g_off);
    cudaGetSymbolAddress((void**)&p_attnl, g_attnl);
    cudaGetSymbolAddress((void**)&p_samp,  g_samp);

    const int M = MROWS;            // 43520, divisible by 128
    dim3 blk(256);

    // 1) value projection: X @ W_val + b_val  (N=256)
    sgemm_bias<<<dim3(256 / BN, M / BM), blk>>>(xin, W_val, b_val, p_value, M, 256, 256);

    // 2) sampling offsets: Q @ W_off + b_off  (N=256)
    sgemm_bias<<<dim3(256 / BN, M / BM), blk>>>(query, W_off, b_off, p_off, M, 256, 256);

    // 3) attention logits: Q @ W_attn + b_attn  (N=128)
    sgemm_bias<<<dim3(128 / BN, M / BM), blk>>>(query, W_attn, b_attn, p_attnl, M, 128, 256);

    // 4) fused softmax + deformable bilinear sampling
    {
        const int warps = MROWS * NHEADS;          // 348160
        const int blocks = (warps + 7) / 8;        // 8 warps / block
        deform_sample<<<blocks, 256>>>(refp);
    }

    // 5) output projection: samp @ W_out + b_out  (N=256)
    sgemm_bias<<<dim3(256 / BN, M / BM), blk>>>(p_samp, W_out, b_out, out, M, 256, 256);
}

// round 2
// speedup vs baseline: 1.2511x; 1.2511x over previous
#include <cuda_runtime.h>
#include <math.h>

// ---------------- problem constants ----------------
#define BATCH    2
#define LQ       21760            // 128^2+64^2+32^2+16^2
#define LEN_IN   21760
#define DMODEL   256
#define NHEADS   8
#define HDIM     32
#define MROWS    (BATCH*LQ)       // 43520
#define NQP      384              // fused off(256)+attn(128) projection width

// level geometry
__device__ __constant__ int c_lvlWH[4]   = {128, 64, 32, 16};
__device__ __constant__ int c_lvlBase[4] = {0, 16384, 20480, 21504};

// ---------------- scratch (device globals; no allocation allowed) ----------------
__device__ float g_value[(size_t)BATCH*LEN_IN*DMODEL];   // value projection
__device__ float g_qproj[(size_t)MROWS*NQP];             // [off(256) | attn logits(128)]
__device__ float g_samp [(size_t)MROWS*DMODEL];          // deformable-sampled output
__device__ float g_Wcat [(size_t)DMODEL*NQP];            // concat(W_off, W_attn)
__device__ float g_bcat [NQP];

// ---------------- packed f32x2 FMA (rt_SMSP=1 vs 2 for 3-reg FFMA) ----------------
__device__ __forceinline__ unsigned long long fma2(unsigned long long a,
                                                   unsigned long long b,
                                                   unsigned long long c) {
    unsigned long long d;
    asm("fma.rn.f32x2 %0, %1, %2, %3;" : "=l"(d) : "l"(a), "l"(b), "l"(c));
    return d;
}

// ---------------- weight concat kernel (tiny) ----------------
__global__ void concat_w(const float* __restrict__ W_off, const float* __restrict__ b_off,
                         const float* __restrict__ W_attn, const float* __restrict__ b_attn)
{
    int i = blockIdx.x * 256 + threadIdx.x;
    if (i < DMODEL * NQP) {
        int r = i / NQP, c = i % NQP;
        g_Wcat[i] = (c < 256) ? W_off[r * 256 + c] : W_attn[r * 128 + (c - 256)];
    }
    if (i < NQP) g_bcat[i] = (i < 256) ? b_off[i] : b_attn[i - 256];
}

// ---------------- SGEMM with f32x2, double-buffered smem ----------------
// C[M,N] = A[M,K] * W[K,N] + bias[N].  M%128==0, N%128==0, K%8==0.
#define BM 128
#define BN 128
#define BK 8

__global__ __launch_bounds__(256, 2)
void sgemm_bias_f32x2(const float* __restrict__ A, const float* __restrict__ W,
                      const float* __restrict__ bias, float* __restrict__ C,
                      int M, int N, int K)
{
    // A tile stored DUPLICATED: As[s][k][2m] = As[s][k][2m+1] = A[bm+m][k0+k]
    __shared__ float As[2][BK][2 * BM];     // 16 KB
    __shared__ float Bs[2][BK][BN];         //  8 KB

    const int tid  = threadIdx.x;
    const int bm   = blockIdx.y * BM;
    const int bn   = blockIdx.x * BN;
    const int tcol = tid & 15;              // output cols tcol*8 .. +7
    const int trow = tid >> 4;              // output rows trow*8 .. +7

    // loader mapping: A tile is 128x8 floats (256 float4s? no: 128*8=1024 = 256 x float4)
    const int arow  = tid >> 1;             // 0..127
    const int akc4  = (tid & 1) * 4;        // k offset 0 or 4
    const int brow  = tid >> 5;             // 0..7
    const int bcol4 = (tid & 31) * 4;       // 0..124

    unsigned long long acc[8][4];
    #pragma unroll
    for (int i = 0; i < 8; i++)
        #pragma unroll
        for (int j = 0; j < 4; j++) acc[i][j] = 0ull;

    const float* Aptr = A + (size_t)(bm + arow) * K + akc4;
    const float* Bptr = W + (size_t)brow * N + bn + bcol4;

    // prologue: stage 0
    {
        float4 av = *(const float4*)Aptr;
        float4 bv = *(const float4*)Bptr;
        #pragma unroll
        for (int j = 0; j < 4; j++) {
            float f = ((const float*)&av)[j];
            *(float2*)&As[0][akc4 + j][2 * arow] = make_float2(f, f);
        }
        *(float4*)&Bs[0][brow][bcol4] = bv;
    }
    __syncthreads();

    const int nsteps = K / BK;
    for (int ks = 0; ks < nsteps; ks++) {
        const int cur = ks & 1;
        float4 anx, bnx;
        const bool more = (ks + 1 < nsteps);
        if (more) {
            anx = *(const float4*)(Aptr + (size_t)(ks + 1) * BK);
            bnx = *(const float4*)(Bptr + (size_t)(ks + 1) * BK * N);
        }

        #pragma unroll
        for (int k = 0; k < BK; k++) {
            unsigned long long a2[8], b2[4];
            {
                ulonglong2 t0 = *(const ulonglong2*)&As[cur][k][trow * 16 + 0];
                ulonglong2 t1 = *(const ulonglong2*)&As[cur][k][trow * 16 + 4];
                ulonglong2 t2 = *(const ulonglong2*)&As[cur][k][trow * 16 + 8];
                ulonglong2 t3 = *(const ulonglong2*)&As[cur][k][trow * 16 + 12];
                a2[0] = t0.x; a2[1] = t0.y; a2[2] = t1.x; a2[3] = t1.y;
                a2[4] = t2.x; a2[5] = t2.y; a2[6] = t3.x; a2[7] = t3.y;
                ulonglong2 u0 = *(const ulonglong2*)&Bs[cur][k][tcol * 8 + 0];
                ulonglong2 u1 = *(const ulonglong2*)&Bs[cur][k][tcol * 8 + 4];
                b2[0] = u0.x; b2[1] = u0.y; b2[2] = u1.x; b2[3] = u1.y;
            }
            #pragma unroll
            for (int i = 0; i < 8; i++)
                #pragma unroll
                for (int j = 0; j < 4; j++)
                    acc[i][j] = fma2(a2[i], b2[j], acc[i][j]);
        }

        if (more) {
            const int nxt = cur ^ 1;
            #pragma unroll
            for (int j = 0; j < 4; j++) {
                float f = ((const float*)&anx)[j];
                *(float2*)&As[nxt][akc4 + j][2 * arow] = make_float2(f, f);
            }
            *(float4*)&Bs[nxt][brow][bcol4] = bnx;
        }
        __syncthreads();
    }

    // epilogue
    const float4 bv0 = *(const float4*)(bias + bn + tcol * 8);
    const float4 bv1 = *(const float4*)(bias + bn + tcol * 8 + 4);
    #pragma unroll
    for (int i = 0; i < 8; i++) {
        float* crow = C + (size_t)(bm + trow * 8 + i) * N + bn + tcol * 8;
        float2 p0 = *(float2*)&acc[i][0];
        float2 p1 = *(float2*)&acc[i][1];
        float2 p2 = *(float2*)&acc[i][2];
        float2 p3 = *(float2*)&acc[i][3];
        float4 v0 = make_float4(p0.x + bv0.x, p0.y + bv0.y, p1.x + bv0.z, p1.y + bv0.w);
        float4 v1 = make_float4(p2.x + bv1.x, p2.y + bv1.y, p3.x + bv1.z, p3.y + bv1.w);
        *(float4*)(crow + 0) = v0;
        *(float4*)(crow + 4) = v1;
    }
}

// ---------------- fused softmax + deformable bilinear sampling ----------------
// One warp per (b, q, head).
// Phase A: lanes 0..15 (lane = point) compute byte-offset + weight for the 4
//          bilinear corners (weight folded with softmax attn + validity; index
//          clamped so no branches in the gather loop) -> shared.
// Phase B: lane = (corner g=lane>>3, channel-quad s=lane&7); 16 iterations of
//          {2x LDS, 1x LDG.128, 4x FFMA}; xor-reduce over corners; lanes 0..7
//          store one float4 each.
__global__ __launch_bounds__(256)
void deform_sample(const float* __restrict__ refp)
{
    __shared__ int   s_idx[8][64];
    __shared__ float s_w  [8][64];

    const int wInB = threadIdx.x >> 5;
    const int lane = threadIdx.x & 31;
    const int warp = blockIdx.x * 8 + wInB;   // grid sized exactly: MROWS*NHEADS/8 blocks

    const int h  = warp & 7;
    const int bq = warp >> 3;
    const int b  = (bq >= LQ) ? 1 : 0;

    const float* row = g_qproj + (size_t)bq * NQP;

    // softmax over 16 logits (lanes 0..15 hold point p's weight)
    float logit = (lane < 16) ? row[256 + h * 16 + lane] : -INFINITY;
    float mx = logit;
    #pragma unroll
    for (int s = 16; s; s >>= 1) mx = fmaxf(mx, __shfl_xor_sync(0xffffffffu, mx, s));
    float e = (lane < 16) ? __expf(logit - mx) : 0.f;
    float sum = e;
    #pragma unroll
    for (int s = 16; s; s >>= 1) sum += __shfl_xor_sync(0xffffffffu, sum, s);
    const float watt = e / sum;

    // raw per-lane data
    const float offv = row[h * 32 + lane];                       // 32 offset floats
    const float refv = (lane < 8) ? refp[(size_t)bq * 8 + lane] : 0.f;

    // gather this lane's point parameters (lane = point p for p<16)
    const float ox = __shfl_sync(0xffffffffu, offv, (2 * lane) & 31);
    const float oy = __shfl_sync(0xffffffffu, offv, (2 * lane + 1) & 31);
    const int   l  = (lane >> 2) & 3;
    const float rx = __shfl_sync(0xffffffffu, refv, 2 * l);
    const float ry = __shfl_sync(0xffffffffu, refv, 2 * l + 1);

    if (lane < 16) {
        const int   WH   = c_lvlWH[l];
        const int   base = c_lvlBase[l];
        const float Wf   = (float)WH;

        const float ix = fmaf(rx, Wf, ox) - 0.5f;
        const float iy = fmaf(ry, Wf, oy) - 0.5f;
        const float x0f = floorf(ix), y0f = floorf(iy);
        const int   x0 = (int)x0f,    y0 = (int)y0f;
        const float fx = ix - x0f,    fy = iy - y0f;

        const int x1 = x0 + 1, y1 = y0 + 1;
        const float vx0 = (x0 >= 0 && x0 < WH) ? 1.f : 0.f;
        const float vx1 = (x1 >= 0 && x1 < WH) ? 1.f : 0.f;
        const float vy0 = (y0 >= 0 && y0 < WH) ? 1.f : 0.f;
        const float vy1 = (y1 >= 0 && y1 < WH) ? 1.f : 0.f;

        const int cx0 = min(max(x0, 0), WH - 1);
        const int cx1 = min(max(x1, 0), WH - 1);
        const int cy0 = min(max(y0, 0), WH - 1);
        const int cy1 = min(max(y1, 0), WH - 1);

        // byte offsets (row stride in g_value = DMODEL*4 = 1024 B)
        s_idx[wInB][lane * 4 + 0] = (base + cy0 * WH + cx0) << 10;
        s_idx[wInB][lane * 4 + 1] = (base + cy0 * WH + cx1) << 10;
        s_idx[wInB][lane * 4 + 2] = (base + cy1 * WH + cx0) << 10;
        s_idx[wInB][lane * 4 + 3] = (base + cy1 * WH + cx1) << 10;

        const float aw = watt;
        s_w[wInB][lane * 4 + 0] = (1.f - fx) * (1.f - fy) * vy0 * vx0 * aw;
        s_w[wInB][lane * 4 + 1] = fx * (1.f - fy) * vy0 * vx1 * aw;
        s_w[wInB][lane * 4 + 2] = (1.f - fx) * fy * vy1 * vx0 * aw;
        s_w[wInB][lane * 4 + 3] = fx * fy * vy1 * vx1 * aw;
    }
    __syncwarp();

    // gather phase
    const int g = lane >> 3;       // corner 0..3
    const int s = lane & 7;        // channel quad 0..7
    const char* vb = (const char*)(g_value + ((size_t)b * LEN_IN) * DMODEL + h * HDIM) + s * 16;

    float4 acc = make_float4(0.f, 0.f, 0.f, 0.f);
    #pragma unroll
    for (int t = 0; t < 16; t++) {
        const int   pc  = t * 4 + g;
        const int   off = s_idx[wInB][pc];
        const float w   = s_w[wInB][pc];
        const float4 v  = *(const float4*)(vb + off);
        acc.x = fmaf(w, v.x, acc.x);
        acc.y = fmaf(w, v.y, acc.y);
        acc.z = fmaf(w, v.z, acc.z);
        acc.w = fmaf(w, v.w, acc.w);
    }

    // reduce over corner g (lanes xor 8, xor 16)
    #pragma unroll
    for (int sh = 8; sh <= 16; sh <<= 1) {
        acc.x += __shfl_xor_sync(0xffffffffu, acc.x, sh);
        acc.y += __shfl_xor_sync(0xffffffffu, acc.y, sh);
        acc.z += __shfl_xor_sync(0xffffffffu, acc.z, sh);
        acc.w += __shfl_xor_sync(0xffffffffu, acc.w, sh);
    }
    if (lane < 8)
        *(float4*)(g_samp + (size_t)bq * DMODEL + h * HDIM + s * 4) = acc;
}

// ---------------- launch ----------------
extern "C" void kernel_launch(void* const* d_in, const int* in_sizes, int n_in,
                              void* d_out, int out_size)
{
    (void)in_sizes; (void)n_in; (void)out_size;
    const float* query  = (const float*)d_in[0];
    const float* refp   = (const float*)d_in[1];
    const float* xin    = (const float*)d_in[2];
    const float* W_off  = (const float*)d_in[3];
    const float* b_off  = (const float*)d_in[4];
    const float* W_attn = (const float*)d_in[5];
    const float* b_attn = (const float*)d_in[6];
    const float* W_val  = (const float*)d_in[7];
    const float* b_val  = (const float*)d_in[8];
    const float* W_out  = (const float*)d_in[9];
    const float* b_out  = (const float*)d_in[10];
    float* out = (float*)d_out;

    float *p_value, *p_qproj, *p_samp, *p_Wcat, *p_bcat;
    cudaGetSymbolAddress((void**)&p_value, g_value);
    cudaGetSymbolAddress((void**)&p_qproj, g_qproj);
    cudaGetSymbolAddress((void**)&p_samp,  g_samp);
    cudaGetSymbolAddress((void**)&p_Wcat,  g_Wcat);
    cudaGetSymbolAddress((void**)&p_bcat,  g_bcat);

    const int M = MROWS;
    dim3 blk(256);

    // 0) concat W_off|W_attn
    concat_w<<<(DMODEL * NQP + 255) / 256, 256>>>(W_off, b_off, W_attn, b_attn);

    // 1) value projection (N=256)
    sgemm_bias_f32x2<<<dim3(256 / BN, M / BM), blk>>>(xin, W_val, b_val, p_value, M, 256, 256);

    // 2) fused query projection (N=384): offsets + attn logits
    sgemm_bias_f32x2<<<dim3(NQP / BN, M / BM), blk>>>(query, p_Wcat, p_bcat, p_qproj, M, NQP, 256);

    // 3) fused softmax + deformable sampling
    deform_sample<<<(MROWS * NHEADS) / 8, 256>>>(refp);

    // 4) output projection (N=256)
    sgemm_bias_f32x2<<<dim3(256 / BN, M / BM), blk>>>(p_samp, W_out, b_out, out, M, 256, 256);
}

// round 4
// speedup vs baseline: 2.6186x; 2.0930x over previous
#include <cuda_runtime.h>
#include <cuda_fp16.h>
#include <math.h>
#include <stdint.h>

// ---------------- problem constants ----------------
#define BATCH    2
#define LQ       21760
#define LEN_IN   21760
#define DMODEL   256
#define NHEADS   8
#define HDIM     32
#define MROWS    (BATCH*LQ)       // 43520
#define NQP      384              // fused off(256)+attn(128)
#define KDIM     256

// level geometry
__device__ __constant__ int c_lvlWH[4]   = {128, 64, 32, 16};
__device__ __constant__ int c_lvlBase[4] = {0, 16384, 20480, 21504};

// ---------------- scratch ----------------
__device__ float g_value[(size_t)BATCH*LEN_IN*DMODEL];
__device__ float g_qproj[(size_t)MROWS*NQP];
__device__ float g_samp [(size_t)MROWS*DMODEL];
// weights split hi/lo in natural [k][n] layout (fp16)
__device__ __half g_Wq_hi[KDIM*NQP],    g_Wq_lo[KDIM*NQP];
__device__ __half g_Wv_hi[KDIM*DMODEL], g_Wv_lo[KDIM*DMODEL];
__device__ __half g_Wo_hi[KDIM*DMODEL], g_Wo_lo[KDIM*DMODEL];
__device__ float g_bq[NQP];

// ---------------- PTX helpers ----------------
__device__ __forceinline__ uint32_t smem_u32(const void* p) {
    uint32_t a;
    asm("{ .reg .u64 t; cvta.to.shared.u64 t, %1; cvt.u32.u64 %0, t; }" : "=r"(a) : "l"(p));
    return a;
}
__device__ __forceinline__ void ldsm4(uint32_t* r, uint32_t a) {
    asm volatile("ldmatrix.sync.aligned.m8n8.x4.shared.b16 {%0,%1,%2,%3}, [%4];"
                 : "=r"(r[0]), "=r"(r[1]), "=r"(r[2]), "=r"(r[3]) : "r"(a));
}
__device__ __forceinline__ void ldsm4t(uint32_t* r, uint32_t a) {
    asm volatile("ldmatrix.sync.aligned.m8n8.x4.trans.shared.b16 {%0,%1,%2,%3}, [%4];"
                 : "=r"(r[0]), "=r"(r[1]), "=r"(r[2]), "=r"(r[3]) : "r"(a));
}
__device__ __forceinline__ void mma16816(float* c, const uint32_t* a, const uint32_t* b) {
    asm volatile("mma.sync.aligned.m16n8k16.row.col.f32.f16.f16.f32 "
                 "{%0,%1,%2,%3}, {%4,%5,%6,%7}, {%8,%9}, {%0,%1,%2,%3};"
                 : "+f"(c[0]), "+f"(c[1]), "+f"(c[2]), "+f"(c[3])
                 : "r"(a[0]), "r"(a[1]), "r"(a[2]), "r"(a[3]), "r"(b[0]), "r"(b[1]));
}
__device__ __forceinline__ uint32_t packh(__half a, __half b) {
    __half2 t = __halves2half2(a, b);
    return *(uint32_t*)&t;
}

// ---------------- weight prep: split fp16 hi/lo, [k][n] layout ----------------
__global__ void prep_weights(const float* __restrict__ W_off, const float* __restrict__ b_off,
                             const float* __restrict__ W_attn, const float* __restrict__ b_attn,
                             const float* __restrict__ W_val, const float* __restrict__ W_out)
{
    const int i = blockIdx.x * 256 + threadIdx.x;
    const int NQ = KDIM * NQP;      // 98304
    const int NV = KDIM * DMODEL;   // 65536
    float w; __half *ph, *pl; int idx;
    if (i < NQ) {
        int k = i / NQP, n = i % NQP;
        w = (n < 256) ? W_off[k * 256 + n] : W_attn[k * 128 + (n - 256)];
        ph = g_Wq_hi; pl = g_Wq_lo; idx = i;
    } else if (i < NQ + NV) {
        idx = i - NQ;
        w = W_val[idx];
        ph = g_Wv_hi; pl = g_Wv_lo;
    } else if (i < NQ + 2 * NV) {
        idx = i - NQ - NV;
        w = W_out[idx];
        ph = g_Wo_hi; pl = g_Wo_lo;
    } else return;
    __half hi = __float2half_rn(w);
    __half lo = __float2half_rn(w - __half2float(hi));
    ph[idx] = hi; pl[idx] = lo;
    if (i < NQP) g_bq[i] = (i < 256) ? b_off[i] : b_attn[i - 256];
}

// ---------------- HMMA GEMM: C[M,N] = A[M,256]*W[256,N] + bias ----------------
// BM=128, BN=128 per CTA; 8 warps, warp tile 32x64; K chunked 4x64.
// fp16 3-pass split: ah*bh + ah*bl + al*bh, fp32 accumulate.
#define ASTRIDE 144   // bytes per A smem row (64 fp16 + 8 pad)
#define BSTRIDE 272   // bytes per B smem row (128 fp16 + 8 pad)
#define SA_H 0
#define SA_L 18432            // 128*144
#define SB_H 36864
#define SB_L (36864+17408)    // 64*272
#define SMEM_GEMM (36864+2*17408)   // 71680

__global__ __launch_bounds__(256, 2)
void gemm_hmma(const float* __restrict__ A,
               const __half* __restrict__ Wh, const __half* __restrict__ Wl,
               const float* __restrict__ bias, float* __restrict__ C, int N)
{
    extern __shared__ __align__(16) char dsm[];
    const uint32_t sb = smem_u32(dsm);

    const int tid  = threadIdx.x;
    const int wid  = tid >> 5;
    const int lane = tid & 31;
    const int bm   = blockIdx.y * 128;
    const int bn   = blockIdx.x * 128;
    const int m0   = (wid & 3) * 32;
    const int n0w  = (wid >> 2) * 64;

    float acc[2][8][4];
    #pragma unroll
    for (int i = 0; i < 2; i++)
        #pragma unroll
        for (int j = 0; j < 8; j++)
            #pragma unroll
            for (int q = 0; q < 4; q++) acc[i][j][q] = 0.f;

    // per-lane ldmatrix base addresses
    const uint32_t aOff = (uint32_t)((m0 + (lane & 15)) * ASTRIDE + (lane >> 4) * 16);
    const uint32_t aHiB = sb + SA_H + aOff;
    const uint32_t aLoB = sb + SA_L + aOff;
    const uint32_t bOff = (uint32_t)(((lane & 7) + ((lane >> 3) & 1) * 8) * BSTRIDE
                                     + (lane >> 4) * 16 + n0w * 2);
    const uint32_t bHiB = sb + SB_H + bOff;
    const uint32_t bLoB = sb + SB_L + bOff;

    for (int c = 0; c < 4; c++) {
        // ---- load A chunk: 128 rows x 64 fp32 -> fp16 hi/lo ----
        #pragma unroll
        for (int it = 0; it < 8; it++) {
            int idx = tid + it * 256;
            int r   = idx >> 4;
            int k4  = (idx & 15) * 4;
            float4 a = *(const float4*)(A + (size_t)(bm + r) * KDIM + c * 64 + k4);
            __half h0 = __float2half_rn(a.x), h1 = __float2half_rn(a.y);
            __half h2 = __float2half_rn(a.z), h3 = __float2half_rn(a.w);
            __half l0 = __float2half_rn(a.x - __half2float(h0));
            __half l1 = __float2half_rn(a.y - __half2float(h1));
            __half l2 = __float2half_rn(a.z - __half2float(h2));
            __half l3 = __float2half_rn(a.w - __half2float(h3));
            uint32_t so = (uint32_t)(r * ASTRIDE + k4 * 2);
            asm volatile("st.shared.v2.b32 [%0], {%1, %2};"
                         :: "r"(sb + SA_H + so), "r"(packh(h0, h1)), "r"(packh(h2, h3)) : "memory");
            asm volatile("st.shared.v2.b32 [%0], {%1, %2};"
                         :: "r"(sb + SA_L + so), "r"(packh(l0, l1)), "r"(packh(l2, l3)) : "memory");
        }
        // ---- load B chunk: 64 rows(k) x 128 cols(n) fp16 hi+lo ----
        #pragma unroll
        for (int it = 0; it < 4; it++) {
            int idx = tid + it * 256;
            int k   = idx >> 4;
            int n8  = (idx & 15) * 8;
            const uint4 vh = *(const uint4*)(Wh + (size_t)(c * 64 + k) * N + bn + n8);
            const uint4 vl = *(const uint4*)(Wl + (size_t)(c * 64 + k) * N + bn + n8);
            uint32_t so = (uint32_t)(k * BSTRIDE + n8 * 2);
            asm volatile("st.shared.v4.b32 [%0], {%1, %2, %3, %4};"
                         :: "r"(sb + SB_H + so), "r"(vh.x), "r"(vh.y), "r"(vh.z), "r"(vh.w) : "memory");
            asm volatile("st.shared.v4.b32 [%0], {%1, %2, %3, %4};"
                         :: "r"(sb + SB_L + so), "r"(vl.x), "r"(vl.y), "r"(vl.z), "r"(vl.w) : "memory");
        }
        __syncthreads();

        // ---- compute: 4 k16 steps ----
        #pragma unroll
        for (int ks = 0; ks < 4; ks++) {
            uint32_t ah[2][4], al[2][4];
            ldsm4(ah[0], aHiB + ks * 32);
            ldsm4(ah[1], aHiB + 16 * ASTRIDE + ks * 32);
            ldsm4(al[0], aLoB + ks * 32);
            ldsm4(al[1], aLoB + 16 * ASTRIDE + ks * 32);
            #pragma unroll
            for (int hh = 0; hh < 2; hh++) {           // n32 halves
                uint32_t bh[8], bl[8];
                ldsm4t(bh,     bHiB + ks * (16 * BSTRIDE) + hh * 64);
                ldsm4t(bh + 4, bHiB + ks * (16 * BSTRIDE) + hh * 64 + 32);
                ldsm4t(bl,     bLoB + ks * (16 * BSTRIDE) + hh * 64);
                ldsm4t(bl + 4, bLoB + ks * (16 * BSTRIDE) + hh * 64 + 32);
                // pass 1: ah * bh
                #pragma unroll
                for (int j = 0; j < 4; j++)
                    #pragma unroll
                    for (int i = 0; i < 2; i++)
                        mma16816(acc[i][hh * 4 + j], ah[i], bh + j * 2);
                // pass 2: ah * bl
                #pragma unroll
                for (int j = 0; j < 4; j++)
                    #pragma unroll
                    for (int i = 0; i < 2; i++)
                        mma16816(acc[i][hh * 4 + j], ah[i], bl + j * 2);
                // pass 3: al * bh
                #pragma unroll
                for (int j = 0; j < 4; j++)
                    #pragma unroll
                    for (int i = 0; i < 2; i++)
                        mma16816(acc[i][hh * 4 + j], al[i], bh + j * 2);
            }
        }
        __syncthreads();
    }

    // ---- epilogue ----
    #pragma unroll
    for (int i = 0; i < 2; i++) {
        const int r0 = bm + m0 + i * 16 + (lane >> 2);
        #pragma unroll
        for (int j = 0; j < 8; j++) {
            const int cc = bn + n0w + j * 8 + (lane & 3) * 2;
            const float2 bv = *(const float2*)(bias + cc);
            float2 v0 = make_float2(acc[i][j][0] + bv.x, acc[i][j][1] + bv.y);
            float2 v1 = make_float2(acc[i][j][2] + bv.x, acc[i][j][3] + bv.y);
            *(float2*)(C + (size_t)r0 * N + cc) = v0;
            *(float2*)(C + (size_t)(r0 + 8) * N + cc) = v1;
        }
    }
}

// ---------------- fused softmax + deformable bilinear sampling ----------------
__global__ __launch_bounds__(256)
void deform_sample(const float* __restrict__ refp)
{
    __shared__ int   s_idx[8][64];
    __shared__ float s_w  [8][64];

    const int wInB = threadIdx.x >> 5;
    const int lane = threadIdx.x & 31;
    const int warp = blockIdx.x * 8 + wInB;

    const int h  = warp & 7;
    const int bq = warp >> 3;
    const int b  = (bq >= LQ) ? 1 : 0;

    const float* row = g_qproj + (size_t)bq * NQP;

    float logit = (lane < 16) ? row[256 + h * 16 + lane] : -INFINITY;
    float mx = logit;
    #pragma unroll
    for (int s = 16; s; s >>= 1) mx = fmaxf(mx, __shfl_xor_sync(0xffffffffu, mx, s));
    float e = (lane < 16) ? __expf(logit - mx) : 0.f;
    float sum = e;
    #pragma unroll
    for (int s = 16; s; s >>= 1) sum += __shfl_xor_sync(0xffffffffu, sum, s);
    const float watt = e / sum;

    const float offv = row[h * 32 + lane];
    const float refv = (lane < 8) ? refp[(size_t)bq * 8 + lane] : 0.f;

    const float ox = __shfl_sync(0xffffffffu, offv, (2 * lane) & 31);
    const float oy = __shfl_sync(0xffffffffu, offv, (2 * lane + 1) & 31);
    const int   l  = (lane >> 2) & 3;
    const float rx = __shfl_sync(0xffffffffu, refv, 2 * l);
    const float ry = __shfl_sync(0xffffffffu, refv, 2 * l + 1);

    if (lane < 16) {
        const int   WH   = c_lvlWH[l];
        const int   base = c_lvlBase[l];
        const float Wf   = (float)WH;

        const float ix = fmaf(rx, Wf, ox) - 0.5f;
        const float iy = fmaf(ry, Wf, oy) - 0.5f;
        const float x0f = floorf(ix), y0f = floorf(iy);
        const int   x0 = (int)x0f,    y0 = (int)y0f;
        const float fx = ix - x0f,    fy = iy - y0f;

        const int x1 = x0 + 1, y1 = y0 + 1;
        const float vx0 = (x0 >= 0 && x0 < WH) ? 1.f : 0.f;
        const float vx1 = (x1 >= 0 && x1 < WH) ? 1.f : 0.f;
        const float vy0 = (y0 >= 0 && y0 < WH) ? 1.f : 0.f;
        const float vy1 = (y1 >= 0 && y1 < WH) ? 1.f : 0.f;

        const int cx0 = min(max(x0, 0), WH - 1);
        const int cx1 = min(max(x1, 0), WH - 1);
        const int cy0 = min(max(y0, 0), WH - 1);
        const int cy1 = min(max(y1, 0), WH - 1);

        s_idx[wInB][lane * 4 + 0] = (base + cy0 * WH + cx0) << 10;
        s_idx[wInB][lane * 4 + 1] = (base + cy0 * WH + cx1) << 10;
        s_idx[wInB][lane * 4 + 2] = (base + cy1 * WH + cx0) << 10;
        s_idx[wInB][lane * 4 + 3] = (base + cy1 * WH + cx1) << 10;

        s_w[wInB][lane * 4 + 0] = (1.f - fx) * (1.f - fy) * vy0 * vx0 * watt;
        s_w[wInB][lane * 4 + 1] = fx * (1.f - fy) * vy0 * vx1 * watt;
        s_w[wInB][lane * 4 + 2] = (1.f - fx) * fy * vy1 * vx0 * watt;
        s_w[wInB][lane * 4 + 3] = fx * fy * vy1 * vx1 * watt;
    }
    __syncwarp();

    const int g = lane >> 3;
    const int s = lane & 7;
    const char* vb = (const char*)(g_value + ((size_t)b * LEN_IN) * DMODEL + h * HDIM) + s * 16;

    float4 acc = make_float4(0.f, 0.f, 0.f, 0.f);
    #pragma unroll
    for (int t = 0; t < 16; t++) {
        const int   pc  = t * 4 + g;
        const int   off = s_idx[wInB][pc];
        const float w   = s_w[wInB][pc];
        const float4 v  = *(const float4*)(vb + off);
        acc.x = fmaf(w, v.x, acc.x);
        acc.y = fmaf(w, v.y, acc.y);
        acc.z = fmaf(w, v.z, acc.z);
        acc.w = fmaf(w, v.w, acc.w);
    }
    #pragma unroll
    for (int sh = 8; sh <= 16; sh <<= 1) {
        acc.x += __shfl_xor_sync(0xffffffffu, acc.x, sh);
        acc.y += __shfl_xor_sync(0xffffffffu, acc.y, sh);
        acc.z += __shfl_xor_sync(0xffffffffu, acc.z, sh);
        acc.w += __shfl_xor_sync(0xffffffffu, acc.w, sh);
    }
    if (lane < 8)
        *(float4*)(g_samp + (size_t)bq * DMODEL + h * HDIM + s * 4) = acc;
}

// ---------------- launch ----------------
extern "C" void kernel_launch(void* const* d_in, const int* in_sizes, int n_in,
                              void* d_out, int out_size)
{
    (void)in_sizes; (void)n_in; (void)out_size;
    const float* query  = (const float*)d_in[0];
    const float* refp   = (const float*)d_in[1];
    const float* xin    = (const float*)d_in[2];
    const float* W_off  = (const float*)d_in[3];
    const float* b_off  = (const float*)d_in[4];
    const float* W_attn = (const float*)d_in[5];
    const float* b_attn = (const float*)d_in[6];
    const float* W_val  = (const float*)d_in[7];
    const float* b_val  = (const float*)d_in[8];
    const float* W_out  = (const float*)d_in[9];
    const float* b_out  = (const float*)d_in[10];
    float* out = (float*)d_out;

    float *p_value, *p_qproj, *p_samp, *p_bq;
    __half *p_Wq_hi, *p_Wq_lo, *p_Wv_hi, *p_Wv_lo, *p_Wo_hi, *p_Wo_lo;
    cudaGetSymbolAddress((void**)&p_value, g_value);
    cudaGetSymbolAddress((void**)&p_qproj, g_qproj);
    cudaGetSymbolAddress((void**)&p_samp,  g_samp);
    cudaGetSymbolAddress((void**)&p_bq,    g_bq);
    cudaGetSymbolAddress((void**)&p_Wq_hi, g_Wq_hi);
    cudaGetSymbolAddress((void**)&p_Wq_lo, g_Wq_lo);
    cudaGetSymbolAddress((void**)&p_Wv_hi, g_Wv_hi);
    cudaGetSymbolAddress((void**)&p_Wv_lo, g_Wv_lo);
    cudaGetSymbolAddress((void**)&p_Wo_hi, g_Wo_hi);
    cudaGetSymbolAddress((void**)&p_Wo_lo, g_Wo_lo);

    cudaFuncSetAttribute(gemm_hmma, cudaFuncAttributeMaxDynamicSharedMemorySize, SMEM_GEMM);

    // 0) weight prep
    {
        const int total = KDIM * NQP + 2 * KDIM * DMODEL;   // 229376
        prep_weights<<<(total + 255) / 256, 256>>>(W_off, b_off, W_attn, b_attn, W_val, W_out);
    }

    const int MB = MROWS / 128;   // 340

    // 1) value projection (N=256)
    gemm_hmma<<<dim3(2, MB), 256, SMEM_GEMM>>>(xin, p_Wv_hi, p_Wv_lo, b_val, p_value, 256);

    // 2) fused query projection (N=384)
    gemm_hmma<<<dim3(3, MB), 256, SMEM_GEMM>>>(query, p_Wq_hi, p_Wq_lo, p_bq, p_qproj, NQP);

    // 3) fused softmax + deformable sampling
    deform_sample<<<(MROWS * NHEADS) / 8, 256>>>(refp);

    // 4) output projection (N=256)
    gemm_hmma<<<dim3(2, MB), 256, SMEM_GEMM>>>(p_samp, p_Wo_hi, p_Wo_lo, b_out, out, 256);
}

// round 5
// speedup vs baseline: 2.7483x; 1.0496x over previous
#include <cuda_runtime.h>
#include <cuda_fp16.h>
#include <math.h>
#include <stdint.h>

// ---------------- problem constants ----------------
#define BATCH    2
#define LQ       21760
#define LEN_IN   21760
#define DMODEL   256
#define NHEADS   8
#define HDIM     32
#define MROWS    (BATCH*LQ)       // 43520
#define NQP      384              // fused off(256)+attn(128)
#define KDIM     256

// level geometry
__device__ __constant__ int c_lvlWH[4]   = {128, 64, 32, 16};
__device__ __constant__ int c_lvlBase[4] = {0, 16384, 20480, 21504};

// ---------------- scratch ----------------
// value in fp16, head-major: [b][h][pix][32ch]
__device__ __align__(16) __half g_value_h[(size_t)BATCH*NHEADS*LEN_IN*HDIM];
__device__ float g_qproj[(size_t)MROWS*NQP];
__device__ float g_samp [(size_t)MROWS*DMODEL];
// weights split hi/lo in natural [k][n] layout (fp16)
__device__ __half g_Wq_hi[KDIM*NQP],    g_Wq_lo[KDIM*NQP];
__device__ __half g_Wv_hi[KDIM*DMODEL], g_Wv_lo[KDIM*DMODEL];
__device__ __half g_Wo_hi[KDIM*DMODEL], g_Wo_lo[KDIM*DMODEL];
__device__ float g_bq[NQP];

// ---------------- PTX helpers ----------------
__device__ __forceinline__ uint32_t smem_u32(const void* p) {
    uint32_t a;
    asm("{ .reg .u64 t; cvta.to.shared.u64 t, %1; cvt.u32.u64 %0, t; }" : "=r"(a) : "l"(p));
    return a;
}
__device__ __forceinline__ void ldsm4(uint32_t* r, uint32_t a) {
    asm volatile("ldmatrix.sync.aligned.m8n8.x4.shared.b16 {%0,%1,%2,%3}, [%4];"
                 : "=r"(r[0]), "=r"(r[1]), "=r"(r[2]), "=r"(r[3]) : "r"(a));
}
__device__ __forceinline__ void ldsm4t(uint32_t* r, uint32_t a) {
    asm volatile("ldmatrix.sync.aligned.m8n8.x4.trans.shared.b16 {%0,%1,%2,%3}, [%4];"
                 : "=r"(r[0]), "=r"(r[1]), "=r"(r[2]), "=r"(r[3]) : "r"(a));
}
__device__ __forceinline__ void mma16816(float* c, const uint32_t* a, const uint32_t* b) {
    asm volatile("mma.sync.aligned.m16n8k16.row.col.f32.f16.f16.f32 "
                 "{%0,%1,%2,%3}, {%4,%5,%6,%7}, {%8,%9}, {%0,%1,%2,%3};"
                 : "+f"(c[0]), "+f"(c[1]), "+f"(c[2]), "+f"(c[3])
                 : "r"(a[0]), "r"(a[1]), "r"(a[2]), "r"(a[3]), "r"(b[0]), "r"(b[1]));
}
__device__ __forceinline__ uint32_t packh(__half a, __half b) {
    __half2 t = __halves2half2(a, b);
    return *(uint32_t*)&t;
}

// ---------------- weight prep: split fp16 hi/lo, [k][n] layout ----------------
__global__ void prep_weights(const float* __restrict__ W_off, const float* __restrict__ b_off,
                             const float* __restrict__ W_attn, const float* __restrict__ b_attn,
                             const float* __restrict__ W_val, const float* __restrict__ W_out)
{
    const int i = blockIdx.x * 256 + threadIdx.x;
    const int NQ = KDIM * NQP;      // 98304
    const int NV = KDIM * DMODEL;   // 65536
    float w; __half *ph, *pl; int idx;
    if (i < NQ) {
        int k = i / NQP, n = i % NQP;
        w = (n < 256) ? W_off[k * 256 + n] : W_attn[k * 128 + (n - 256)];
        ph = g_Wq_hi; pl = g_Wq_lo; idx = i;
    } else if (i < NQ + NV) {
        idx = i - NQ;
        w = W_val[idx];
        ph = g_Wv_hi; pl = g_Wv_lo;
    } else if (i < NQ + 2 * NV) {
        idx = i - NQ - NV;
        w = W_out[idx];
        ph = g_Wo_hi; pl = g_Wo_lo;
    } else return;
    __half hi = __float2half_rn(w);
    __half lo = __float2half_rn(w - __half2float(hi));
    ph[idx] = hi; pl[idx] = lo;
    if (i < NQP) g_bq[i] = (i < 256) ? b_off[i] : b_attn[i - 256];
}

// ---------------- HMMA GEMM: C[M,N] = A[M,256]*W[256,N] + bias ----------------
// BM=128, BN=128 per CTA; 8 warps, warp tile 32x64; K chunked 4x64.
// fp16 3-pass split: ah*bh + ah*bl + al*bh, fp32 accumulate.
// HALF_OUT: write fp16 head-major value layout [b][h][pix][32] instead of fp32 C.
#define ASTRIDE 144   // bytes per A smem row (64 fp16 + 8 pad)
#define BSTRIDE 272   // bytes per B smem row (128 fp16 + 8 pad)
#define SA_H 0
#define SA_L 18432            // 128*144
#define SB_H 36864
#define SB_L (36864+17408)    // 64*272
#define SMEM_GEMM (36864+2*17408)   // 71680

template<bool HALF_OUT>
__global__ __launch_bounds__(256, 2)
void gemm_hmma(const float* __restrict__ A,
               const __half* __restrict__ Wh, const __half* __restrict__ Wl,
               const float* __restrict__ bias, float* __restrict__ C, int N)
{
    extern __shared__ __align__(16) char dsm[];
    const uint32_t sb = smem_u32(dsm);

    const int tid  = threadIdx.x;
    const int wid  = tid >> 5;
    const int lane = tid & 31;
    const int bm   = blockIdx.y * 128;
    const int bn   = blockIdx.x * 128;
    const int m0   = (wid & 3) * 32;
    const int n0w  = (wid >> 2) * 64;

    float acc[2][8][4];
    #pragma unroll
    for (int i = 0; i < 2; i++)
        #pragma unroll
        for (int j = 0; j < 8; j++)
            #pragma unroll
            for (int q = 0; q < 4; q++) acc[i][j][q] = 0.f;

    const uint32_t aOff = (uint32_t)((m0 + (lane & 15)) * ASTRIDE + (lane >> 4) * 16);
    const uint32_t aHiB = sb + SA_H + aOff;
    const uint32_t aLoB = sb + SA_L + aOff;
    const uint32_t bOff = (uint32_t)(((lane & 7) + ((lane >> 3) & 1) * 8) * BSTRIDE
                                     + (lane >> 4) * 16 + n0w * 2);
    const uint32_t bHiB = sb + SB_H + bOff;
    const uint32_t bLoB = sb + SB_L + bOff;

    for (int c = 0; c < 4; c++) {
        #pragma unroll
        for (int it = 0; it < 8; it++) {
            int idx = tid + it * 256;
            int r   = idx >> 4;
            int k4  = (idx & 15) * 4;
            float4 a = *(const float4*)(A + (size_t)(bm + r) * KDIM + c * 64 + k4);
            __half h0 = __float2half_rn(a.x), h1 = __float2half_rn(a.y);
            __half h2 = __float2half_rn(a.z), h3 = __float2half_rn(a.w);
            __half l0 = __float2half_rn(a.x - __half2float(h0));
            __half l1 = __float2half_rn(a.y - __half2float(h1));
            __half l2 = __float2half_rn(a.z - __half2float(h2));
            __half l3 = __float2half_rn(a.w - __half2float(h3));
            uint32_t so = (uint32_t)(r * ASTRIDE + k4 * 2);
            asm volatile("st.shared.v2.b32 [%0], {%1, %2};"
                         :: "r"(sb + SA_H + so), "r"(packh(h0, h1)), "r"(packh(h2, h3)) : "memory");
            asm volatile("st.shared.v2.b32 [%0], {%1, %2};"
                         :: "r"(sb + SA_L + so), "r"(packh(l0, l1)), "r"(packh(l2, l3)) : "memory");
        }
        #pragma unroll
        for (int it = 0; it < 4; it++) {
            int idx = tid + it * 256;
            int k   = idx >> 4;
            int n8  = (idx & 15) * 8;
            const uint4 vh = *(const uint4*)(Wh + (size_t)(c * 64 + k) * N + bn + n8);
            const uint4 vl = *(const uint4*)(Wl + (size_t)(c * 64 + k) * N + bn + n8);
            uint32_t so = (uint32_t)(k * BSTRIDE + n8 * 2);
            asm volatile("st.shared.v4.b32 [%0], {%1, %2, %3, %4};"
                         :: "r"(sb + SB_H + so), "r"(vh.x), "r"(vh.y), "r"(vh.z), "r"(vh.w) : "memory");
            asm volatile("st.shared.v4.b32 [%0], {%1, %2, %3, %4};"
                         :: "r"(sb + SB_L + so), "r"(vl.x), "r"(vl.y), "r"(vl.z), "r"(vl.w) : "memory");
        }
        __syncthreads();

        #pragma unroll
        for (int ks = 0; ks < 4; ks++) {
            uint32_t ah[2][4], al[2][4];
            ldsm4(ah[0], aHiB + ks * 32);
            ldsm4(ah[1], aHiB + 16 * ASTRIDE + ks * 32);
            ldsm4(al[0], aLoB + ks * 32);
            ldsm4(al[1], aLoB + 16 * ASTRIDE + ks * 32);
            #pragma unroll
            for (int hh = 0; hh < 2; hh++) {
                uint32_t bh[8], bl[8];
                ldsm4t(bh,     bHiB + ks * (16 * BSTRIDE) + hh * 64);
                ldsm4t(bh + 4, bHiB + ks * (16 * BSTRIDE) + hh * 64 + 32);
                ldsm4t(bl,     bLoB + ks * (16 * BSTRIDE) + hh * 64);
                ldsm4t(bl + 4, bLoB + ks * (16 * BSTRIDE) + hh * 64 + 32);
                #pragma unroll
                for (int j = 0; j < 4; j++)
                    #pragma unroll
                    for (int i = 0; i < 2; i++)
                        mma16816(acc[i][hh * 4 + j], ah[i], bh + j * 2);
                #pragma unroll
                for (int j = 0; j < 4; j++)
                    #pragma unroll
                    for (int i = 0; i < 2; i++)
                        mma16816(acc[i][hh * 4 + j], ah[i], bl + j * 2);
                #pragma unroll
                for (int j = 0; j < 4; j++)
                    #pragma unroll
                    for (int i = 0; i < 2; i++)
                        mma16816(acc[i][hh * 4 + j], al[i], bh + j * 2);
            }
        }
        __syncthreads();
    }

    // ---- epilogue ----
    if (HALF_OUT) {
        // write fp16 head-major value: [b][head][pix][32]
        const int bb = (bm >= LEN_IN) ? 1 : 0;
        const int pixbase = bm - bb * LEN_IN;
        #pragma unroll
        for (int i = 0; i < 2; i++) {
            const int pix = pixbase + m0 + i * 16 + (lane >> 2);
            #pragma unroll
            for (int j = 0; j < 8; j++) {
                const int cc = bn + n0w + j * 8 + (lane & 3) * 2;
                const int head = cc >> 5, chp = cc & 31;
                const float2 bv = *(const float2*)(bias + cc);
                __half* dst = g_value_h
                    + ((size_t)(bb * NHEADS + head) * LEN_IN + pix) * HDIM + chp;
                __half2 v0 = __floats2half2_rn(acc[i][j][0] + bv.x, acc[i][j][1] + bv.y);
                __half2 v1 = __floats2half2_rn(acc[i][j][2] + bv.x, acc[i][j][3] + bv.y);
                *(__half2*)dst = v0;
                *(__half2*)(dst + 8 * HDIM) = v1;   // pix + 8
            }
        }
    } else {
        #pragma unroll
        for (int i = 0; i < 2; i++) {
            const int r0 = bm + m0 + i * 16 + (lane >> 2);
            #pragma unroll
            for (int j = 0; j < 8; j++) {
                const int cc = bn + n0w + j * 8 + (lane & 3) * 2;
                const float2 bv = *(const float2*)(bias + cc);
                float2 v0 = make_float2(acc[i][j][0] + bv.x, acc[i][j][1] + bv.y);
                float2 v1 = make_float2(acc[i][j][2] + bv.x, acc[i][j][3] + bv.y);
                *(float2*)(C + (size_t)r0 * N + cc) = v0;
                *(float2*)(C + (size_t)(r0 + 8) * N + cc) = v1;
            }
        }
    }
}

// ---------------- fused softmax + deformable bilinear sampling ----------------
// fp16 head-major value; one warp per (b,q,head); gather via uint2 (4 ch fp16).
__global__ __launch_bounds__(256)
void deform_sample(const float* __restrict__ refp)
{
    __shared__ uint2 s_pw[8][64];   // {byte offset, weight bits}

    const int wInB = threadIdx.x >> 5;
    const int lane = threadIdx.x & 31;
    const int warp = blockIdx.x * 8 + wInB;

    const int h  = warp & 7;
    const int bq = warp >> 3;
    const int b  = (bq >= LQ) ? 1 : 0;

    const float* row = g_qproj + (size_t)bq * NQP;

    float logit = (lane < 16) ? row[256 + h * 16 + lane] : -INFINITY;
    float mx = logit;
    #pragma unroll
    for (int s = 16; s; s >>= 1) mx = fmaxf(mx, __shfl_xor_sync(0xffffffffu, mx, s));
    float e = (lane < 16) ? __expf(logit - mx) : 0.f;
    float sum = e;
    #pragma unroll
    for (int s = 16; s; s >>= 1) sum += __shfl_xor_sync(0xffffffffu, sum, s);
    const float watt = e / sum;

    const float offv = row[h * 32 + lane];
    const float refv = (lane < 8) ? refp[(size_t)bq * 8 + lane] : 0.f;

    const float ox = __shfl_sync(0xffffffffu, offv, (2 * lane) & 31);
    const float oy = __shfl_sync(0xffffffffu, offv, (2 * lane + 1) & 31);
    const int   l  = (lane >> 2) & 3;
    const float rx = __shfl_sync(0xffffffffu, refv, 2 * l);
    const float ry = __shfl_sync(0xffffffffu, refv, 2 * l + 1);

    if (lane < 16) {
        const int   WH   = c_lvlWH[l];
        const int   base = c_lvlBase[l];
        const float Wf   = (float)WH;

        const float ix = fmaf(rx, Wf, ox) - 0.5f;
        const float iy = fmaf(ry, Wf, oy) - 0.5f;
        const float x0f = floorf(ix), y0f = floorf(iy);
        const int   x0 = (int)x0f,    y0 = (int)y0f;
        const float fx = ix - x0f,    fy = iy - y0f;

        const int x1 = x0 + 1, y1 = y0 + 1;
        const float vx0 = (x0 >= 0 && x0 < WH) ? 1.f : 0.f;
        const float vx1 = (x1 >= 0 && x1 < WH) ? 1.f : 0.f;
        const float vy0 = (y0 >= 0 && y0 < WH) ? 1.f : 0.f;
        const float vy1 = (y1 >= 0 && y1 < WH) ? 1.f : 0.f;

        const int cx0 = min(max(x0, 0), WH - 1);
        const int cx1 = min(max(x1, 0), WH - 1);
        const int cy0 = min(max(y0, 0), WH - 1);
        const int cy1 = min(max(y1, 0), WH - 1);

        // byte offsets: 64 B per pixel (head-major fp16, 32 ch)
        s_pw[wInB][lane * 4 + 0] = make_uint2((uint32_t)(base + cy0 * WH + cx0) << 6,
                                   __float_as_uint((1.f - fx) * (1.f - fy) * vy0 * vx0 * watt));
        s_pw[wInB][lane * 4 + 1] = make_uint2((uint32_t)(base + cy0 * WH + cx1) << 6,
                                   __float_as_uint(fx * (1.f - fy) * vy0 * vx1 * watt));
        s_pw[wInB][lane * 4 + 2] = make_uint2((uint32_t)(base + cy1 * WH + cx0) << 6,
                                   __float_as_uint((1.f - fx) * fy * vy1 * vx0 * watt));
        s_pw[wInB][lane * 4 + 3] = make_uint2((uint32_t)(base + cy1 * WH + cx1) << 6,
                                   __float_as_uint(fx * fy * vy1 * vx1 * watt));
    }
    __syncwarp();

    const int g = lane >> 3;       // corner
    const int s = lane & 7;        // channel quad (4 fp16)
    const char* vbc = (const char*)g_value_h
        + ((size_t)(b * NHEADS + h) * LEN_IN) * (HDIM * 2) + s * 8;

    float4 acc = make_float4(0.f, 0.f, 0.f, 0.f);
    #pragma unroll
    for (int t = 0; t < 16; t++) {
        const uint2 pw = s_pw[wInB][t * 4 + g];
        const float w  = __uint_as_float(pw.y);
        const uint2 v  = *(const uint2*)(vbc + pw.x);
        const float2 f0 = __half22float2(*(const __half2*)&v.x);
        const float2 f1 = __half22float2(*(const __half2*)&v.y);
        acc.x = fmaf(w, f0.x, acc.x);
        acc.y = fmaf(w, f0.y, acc.y);
        acc.z = fmaf(w, f1.x, acc.z);
        acc.w = fmaf(w, f1.y, acc.w);
    }
    #pragma unroll
    for (int sh = 8; sh <= 16; sh <<= 1) {
        acc.x += __shfl_xor_sync(0xffffffffu, acc.x, sh);
        acc.y += __shfl_xor_sync(0xffffffffu, acc.y, sh);
        acc.z += __shfl_xor_sync(0xffffffffu, acc.z, sh);
        acc.w += __shfl_xor_sync(0xffffffffu, acc.w, sh);
    }
    if (lane < 8)
        *(float4*)(g_samp + (size_t)bq * DMODEL + h * HDIM + s * 4) = acc;
}

// ---------------- launch ----------------
extern "C" void kernel_launch(void* const* d_in, const int* in_sizes, int n_in,
                              void* d_out, int out_size)
{
    (void)in_sizes; (void)n_in; (void)out_size;
    const float* query  = (const float*)d_in[0];
    const float* refp   = (const float*)d_in[1];
    const float* xin    = (const float*)d_in[2];
    const float* W_off  = (const float*)d_in[3];
    const float* b_off  = (const float*)d_in[4];
    const float* W_attn = (const float*)d_in[5];
    const float* b_attn = (const float*)d_in[6];
    const float* W_val  = (const float*)d_in[7];
    const float* b_val  = (const float*)d_in[8];
    const float* W_out  = (const float*)d_in[9];
    const float* b_out  = (const float*)d_in[10];
    float* out = (float*)d_out;

    float *p_qproj, *p_samp, *p_bq;
    __half *p_Wq_hi, *p_Wq_lo, *p_Wv_hi, *p_Wv_lo, *p_Wo_hi, *p_Wo_lo;
    cudaGetSymbolAddress((void**)&p_qproj, g_qproj);
    cudaGetSymbolAddress((void**)&p_samp,  g_samp);
    cudaGetSymbolAddress((void**)&p_bq,    g_bq);
    cudaGetSymbolAddress((void**)&p_Wq_hi, g_Wq_hi);
    cudaGetSymbolAddress((void**)&p_Wq_lo, g_Wq_lo);
    cudaGetSymbolAddress((void**)&p_Wv_hi, g_Wv_hi);
    cudaGetSymbolAddress((void**)&p_Wv_lo, g_Wv_lo);
    cudaGetSymbolAddress((void**)&p_Wo_hi, g_Wo_hi);
    cudaGetSymbolAddress((void**)&p_Wo_lo, g_Wo_lo);

    cudaFuncSetAttribute(gemm_hmma<false>, cudaFuncAttributeMaxDynamicSharedMemorySize, SMEM_GEMM);
    cudaFuncSetAttribute(gemm_hmma<true>,  cudaFuncAttributeMaxDynamicSharedMemorySize, SMEM_GEMM);

    // 0) weight prep
    {
        const int total = KDIM * NQP + 2 * KDIM * DMODEL;
        prep_weights<<<(total + 255) / 256, 256>>>(W_off, b_off, W_attn, b_attn, W_val, W_out);
    }

    const int MB = MROWS / 128;   // 340

    // 1) value projection (N=256) -> fp16 head-major
    gemm_hmma<true><<<dim3(2, MB), 256, SMEM_GEMM>>>(xin, p_Wv_hi, p_Wv_lo, b_val, nullptr, 256);

    // 2) fused query projection (N=384)
    gemm_hmma<false><<<dim3(3, MB), 256, SMEM_GEMM>>>(query, p_Wq_hi, p_Wq_lo, p_bq, p_qproj, NQP);

    // 3) fused softmax + deformable sampling
    deform_sample<<<(MROWS * NHEADS) / 8, 256>>>(refp);

    // 4) output projection (N=256)
    gemm_hmma<false><<<dim3(2, MB), 256, SMEM_GEMM>>>(p_samp, p_Wo_hi, p_Wo_lo, b_out, out, 256);
}

// round 6
// speedup vs baseline: 3.2313x; 1.1757x over previous
#include <cuda_runtime.h>
#include <cuda_fp16.h>
#include <math.h>
#include <stdint.h>

// ---------------- problem constants ----------------
#define BATCH    2
#define LQ       21760
#define LEN_IN   21760
#define DMODEL   256
#define NHEADS   8
#define HDIM     32
#define MROWS    (BATCH*LQ)       // 43520
#define NQP      384              // fused off(256)+attn(128)
#define KDIM     256
#define GPB      32               // (q,h) pairs per sampler block

// level geometry
__device__ __constant__ int c_lvlWH[4]   = {128, 64, 32, 16};
__device__ __constant__ int c_lvlBase[4] = {0, 16384, 20480, 21504};

// ---------------- scratch ----------------
// value in fp16, head-major: [b][h][pix][32ch]  (64 B per pixel-row)
__device__ __align__(16) __half g_value_h[(size_t)BATCH*NHEADS*LEN_IN*HDIM];
__device__ float g_qproj[(size_t)MROWS*NQP];
// sampled output in fp16: [bq][256]
__device__ __align__(16) __half g_samp_h[(size_t)MROWS*DMODEL];
// weights split hi/lo in natural [k][n] layout (fp16)
__device__ __half g_Wq_hi[KDIM*NQP],    g_Wq_lo[KDIM*NQP];
__device__ __half g_Wv_hi[KDIM*DMODEL], g_Wv_lo[KDIM*DMODEL];
__device__ __half g_Wo_hi[KDIM*DMODEL], g_Wo_lo[KDIM*DMODEL];
__device__ float g_bq[NQP];

// ---------------- PTX helpers ----------------
__device__ __forceinline__ uint32_t smem_u32(const void* p) {
    uint32_t a;
    asm("{ .reg .u64 t; cvta.to.shared.u64 t, %1; cvt.u32.u64 %0, t; }" : "=r"(a) : "l"(p));
    return a;
}
__device__ __forceinline__ void ldsm4(uint32_t* r, uint32_t a) {
    asm volatile("ldmatrix.sync.aligned.m8n8.x4.shared.b16 {%0,%1,%2,%3}, [%4];"
                 : "=r"(r[0]), "=r"(r[1]), "=r"(r[2]), "=r"(r[3]) : "r"(a));
}
__device__ __forceinline__ void ldsm4t(uint32_t* r, uint32_t a) {
    asm volatile("ldmatrix.sync.aligned.m8n8.x4.trans.shared.b16 {%0,%1,%2,%3}, [%4];"
                 : "=r"(r[0]), "=r"(r[1]), "=r"(r[2]), "=r"(r[3]) : "r"(a));
}
__device__ __forceinline__ void mma16816(float* c, const uint32_t* a, const uint32_t* b) {
    asm volatile("mma.sync.aligned.m16n8k16.row.col.f32.f16.f16.f32 "
                 "{%0,%1,%2,%3}, {%4,%5,%6,%7}, {%8,%9}, {%0,%1,%2,%3};"
                 : "+f"(c[0]), "+f"(c[1]), "+f"(c[2]), "+f"(c[3])
                 : "r"(a[0]), "r"(a[1]), "r"(a[2]), "r"(a[3]), "r"(b[0]), "r"(b[1]));
}
__device__ __forceinline__ uint32_t packh(__half a, __half b) {
    __half2 t = __halves2half2(a, b);
    return *(uint32_t*)&t;
}

// ---------------- weight prep: split fp16 hi/lo, [k][n] layout ----------------
__global__ void prep_weights(const float* __restrict__ W_off, const float* __restrict__ b_off,
                             const float* __restrict__ W_attn, const float* __restrict__ b_attn,
                             const float* __restrict__ W_val, const float* __restrict__ W_out)
{
    const int i = blockIdx.x * 256 + threadIdx.x;
    const int NQ = KDIM * NQP;
    const int NV = KDIM * DMODEL;
    float w; __half *ph, *pl; int idx;
    if (i < NQ) {
        int k = i / NQP, n = i % NQP;
        w = (n < 256) ? W_off[k * 256 + n] : W_attn[k * 128 + (n - 256)];
        ph = g_Wq_hi; pl = g_Wq_lo; idx = i;
    } else if (i < NQ + NV) {
        idx = i - NQ;
        w = W_val[idx];
        ph = g_Wv_hi; pl = g_Wv_lo;
    } else if (i < NQ + 2 * NV) {
        idx = i - NQ - NV;
        w = W_out[idx];
        ph = g_Wo_hi; pl = g_Wo_lo;
    } else return;
    __half hi = __float2half_rn(w);
    __half lo = __float2half_rn(w - __half2float(hi));
    ph[idx] = hi; pl[idx] = lo;
    if (i < NQP) g_bq[i] = (i < 256) ? b_off[i] : b_attn[i - 256];
}

// ---------------- HMMA GEMM ----------------
// MODE 0: fp32 A, 3-pass split, fp32 C out
// MODE 1: fp32 A, 3-pass split, fp16 head-major value out
// MODE 2: fp16 A (exact), 2-pass (ah*bh + ah*bl), fp32 C out
#define ASTRIDE 144
#define BSTRIDE 272
#define SA_H 0
#define SA_L 18432
#define SB_H 36864
#define SB_L (36864+17408)
#define SMEM_GEMM (36864+2*17408)

template<int MODE>
__global__ __launch_bounds__(256, 2)
void gemm_hmma(const float* __restrict__ A, const __half* __restrict__ Ah,
               const __half* __restrict__ Wh, const __half* __restrict__ Wl,
               const float* __restrict__ bias, float* __restrict__ C, int N)
{
    extern __shared__ __align__(16) char dsm[];
    const uint32_t sb = smem_u32(dsm);

    const int tid  = threadIdx.x;
    const int wid  = tid >> 5;
    const int lane = tid & 31;
    const int bm   = blockIdx.y * 128;
    const int bn   = blockIdx.x * 128;
    const int m0   = (wid & 3) * 32;
    const int n0w  = (wid >> 2) * 64;

    float acc[2][8][4];
    #pragma unroll
    for (int i = 0; i < 2; i++)
        #pragma unroll
        for (int j = 0; j < 8; j++)
            #pragma unroll
            for (int q = 0; q < 4; q++) acc[i][j][q] = 0.f;

    const uint32_t aOff = (uint32_t)((m0 + (lane & 15)) * ASTRIDE + (lane >> 4) * 16);
    const uint32_t aHiB = sb + SA_H + aOff;
    const uint32_t aLoB = sb + SA_L + aOff;
    const uint32_t bOff = (uint32_t)(((lane & 7) + ((lane >> 3) & 1) * 8) * BSTRIDE
                                     + (lane >> 4) * 16 + n0w * 2);
    const uint32_t bHiB = sb + SB_H + bOff;
    const uint32_t bLoB = sb + SB_L + bOff;

    for (int c = 0; c < 4; c++) {
        if (MODE == 2) {
            // fp16 A direct load: 128 rows x 64 halves = 1024 uint4
            #pragma unroll
            for (int it = 0; it < 4; it++) {
                int idx = tid + it * 256;
                int r   = idx >> 3;
                int k8  = (idx & 7) * 8;
                const uint4 v = *(const uint4*)(Ah + (size_t)(bm + r) * KDIM + c * 64 + k8);
                uint32_t so = (uint32_t)(r * ASTRIDE + k8 * 2);
                asm volatile("st.shared.v4.b32 [%0], {%1, %2, %3, %4};"
                             :: "r"(sb + SA_H + so), "r"(v.x), "r"(v.y), "r"(v.z), "r"(v.w) : "memory");
            }
        } else {
            #pragma unroll
            for (int it = 0; it < 8; it++) {
                int idx = tid + it * 256;
                int r   = idx >> 4;
                int k4  = (idx & 15) * 4;
                float4 a = *(const float4*)(A + (size_t)(bm + r) * KDIM + c * 64 + k4);
                __half h0 = __float2half_rn(a.x), h1 = __float2half_rn(a.y);
                __half h2 = __float2half_rn(a.z), h3 = __float2half_rn(a.w);
                __half l0 = __float2half_rn(a.x - __half2float(h0));
                __half l1 = __float2half_rn(a.y - __half2float(h1));
                __half l2 = __float2half_rn(a.z - __half2float(h2));
                __half l3 = __float2half_rn(a.w - __half2float(h3));
                uint32_t so = (uint32_t)(r * ASTRIDE + k4 * 2);
                asm volatile("st.shared.v2.b32 [%0], {%1, %2};"
                             :: "r"(sb + SA_H + so), "r"(packh(h0, h1)), "r"(packh(h2, h3)) : "memory");
                asm volatile("st.shared.v2.b32 [%0], {%1, %2};"
                             :: "r"(sb + SA_L + so), "r"(packh(l0, l1)), "r"(packh(l2, l3)) : "memory");
            }
        }
        #pragma unroll
        for (int it = 0; it < 4; it++) {
            int idx = tid + it * 256;
            int k   = idx >> 4;
            int n8  = (idx & 15) * 8;
            const uint4 vh = *(const uint4*)(Wh + (size_t)(c * 64 + k) * N + bn + n8);
            const uint4 vl = *(const uint4*)(Wl + (size_t)(c * 64 + k) * N + bn + n8);
            uint32_t so = (uint32_t)(k * BSTRIDE + n8 * 2);
            asm volatile("st.shared.v4.b32 [%0], {%1, %2, %3, %4};"
                         :: "r"(sb + SB_H + so), "r"(vh.x), "r"(vh.y), "r"(vh.z), "r"(vh.w) : "memory");
            asm volatile("st.shared.v4.b32 [%0], {%1, %2, %3, %4};"
                         :: "r"(sb + SB_L + so), "r"(vl.x), "r"(vl.y), "r"(vl.z), "r"(vl.w) : "memory");
        }
        __syncthreads();

        #pragma unroll
        for (int ks = 0; ks < 4; ks++) {
            uint32_t ah[2][4], al[2][4];
            ldsm4(ah[0], aHiB + ks * 32);
            ldsm4(ah[1], aHiB + 16 * ASTRIDE + ks * 32);
            if (MODE != 2) {
                ldsm4(al[0], aLoB + ks * 32);
                ldsm4(al[1], aLoB + 16 * ASTRIDE + ks * 32);
            }
            #pragma unroll
            for (int hh = 0; hh < 2; hh++) {
                uint32_t bh[8], bl[8];
                ldsm4t(bh,     bHiB + ks * (16 * BSTRIDE) + hh * 64);
                ldsm4t(bh + 4, bHiB + ks * (16 * BSTRIDE) + hh * 64 + 32);
                ldsm4t(bl,     bLoB + ks * (16 * BSTRIDE) + hh * 64);
                ldsm4t(bl + 4, bLoB + ks * (16 * BSTRIDE) + hh * 64 + 32);
                #pragma unroll
                for (int j = 0; j < 4; j++)
                    #pragma unroll
                    for (int i = 0; i < 2; i++)
                        mma16816(acc[i][hh * 4 + j], ah[i], bh + j * 2);
                #pragma unroll
                for (int j = 0; j < 4; j++)
                    #pragma unroll
                    for (int i = 0; i < 2; i++)
                        mma16816(acc[i][hh * 4 + j], ah[i], bl + j * 2);
                if (MODE != 2) {
                    #pragma unroll
                    for (int j = 0; j < 4; j++)
                        #pragma unroll
                        for (int i = 0; i < 2; i++)
                            mma16816(acc[i][hh * 4 + j], al[i], bh + j * 2);
                }
            }
        }
        __syncthreads();
    }

    // ---- epilogue ----
    if (MODE == 1) {
        const int bb = (bm >= LEN_IN) ? 1 : 0;
        const int pixbase = bm - bb * LEN_IN;
        #pragma unroll
        for (int i = 0; i < 2; i++) {
            const int pix = pixbase + m0 + i * 16 + (lane >> 2);
            #pragma unroll
            for (int j = 0; j < 8; j++) {
                const int cc = bn + n0w + j * 8 + (lane & 3) * 2;
                const int head = cc >> 5, chp = cc & 31;
                const float2 bv = *(const float2*)(bias + cc);
                __half* dst = g_value_h
                    + ((size_t)(bb * NHEADS + head) * LEN_IN + pix) * HDIM + chp;
                __half2 v0 = __floats2half2_rn(acc[i][j][0] + bv.x, acc[i][j][1] + bv.y);
                __half2 v1 = __floats2half2_rn(acc[i][j][2] + bv.x, acc[i][j][3] + bv.y);
                *(__half2*)dst = v0;
                *(__half2*)(dst + 8 * HDIM) = v1;
            }
        }
    } else {
        #pragma unroll
        for (int i = 0; i < 2; i++) {
            const int r0 = bm + m0 + i * 16 + (lane >> 2);
            #pragma unroll
            for (int j = 0; j < 8; j++) {
                const int cc = bn + n0w + j * 8 + (lane & 3) * 2;
                const float2 bv = *(const float2*)(bias + cc);
                float2 v0 = make_float2(acc[i][j][0] + bv.x, acc[i][j][1] + bv.y);
                float2 v1 = make_float2(acc[i][j][2] + bv.x, acc[i][j][3] + bv.y);
                *(float2*)(C + (size_t)r0 * N + cc) = v0;
                *(float2*)(C + (size_t)(r0 + 8) * N + cc) = v1;
            }
        }
    }
}

// ---------------- block-staged softmax + deformable sampling ----------------
// Block = 256 threads, GPB=32 (q,h) pairs.
// Phase 1 (all threads): thread = (pair, 2 points) -> 8 corner params to smem.
// Phase 2: warp handles 4 pairs; lane = (corner slot g=lane>>2, quad=lane&3);
//          8 iters of {LDS.64 param, LDG.128 value, 8 cvt, 8 FFMA};
//          xor-reduce over g; fp16 packed store.
__global__ __launch_bounds__(256)
void deform_sample(const float* __restrict__ refp)
{
    __shared__ uint4 s_pw[GPB][32];   // 64 corners x {off,w} = 32 uint4 per pair (16 KB)

    const int tid = threadIdx.x;

    // ---------- phase 1 ----------
    {
        const int pi  = tid >> 3;           // pair in block
        const int sub = tid & 7;            // handles points 2*sub, 2*sub+1
        const int gp  = blockIdx.x * GPB + pi;
        const int h   = gp & 7;
        const int bq  = gp >> 3;
        const float* row = g_qproj + (size_t)bq * NQP;

        // softmax over 16 logits, distributed across 8 threads x 2
        float lg0 = row[256 + h * 16 + 2 * sub];
        float lg1 = row[256 + h * 16 + 2 * sub + 1];
        float mx = fmaxf(lg0, lg1);
        #pragma unroll
        for (int s = 1; s < 8; s <<= 1) mx = fmaxf(mx, __shfl_xor_sync(0xffffffffu, mx, s));
        float e0 = __expf(lg0 - mx), e1 = __expf(lg1 - mx);
        float sm = e0 + e1;
        #pragma unroll
        for (int s = 1; s < 8; s <<= 1) sm += __shfl_xor_sync(0xffffffffu, sm, s);
        const float inv = __frcp_rn(sm);

        // offsets for both points: 4 consecutive floats
        const float4 of = *(const float4*)(row + h * 32 + sub * 4);
        const int l = sub >> 1;             // level (same for both points)
        const float2 rf = *(const float2*)(refp + (size_t)bq * 8 + l * 2);

        const int   WH   = c_lvlWH[l];
        const int   base = c_lvlBase[l];
        const float Wf   = (float)WH;

        #pragma unroll
        for (int pp = 0; pp < 2; pp++) {
            const float ox = pp ? of.z : of.x;
            const float oy = pp ? of.w : of.y;
            const float wat = (pp ? e1 : e0) * inv;

            const float ix = fmaf(rf.x, Wf, ox) - 0.5f;
            const float iy = fmaf(rf.y, Wf, oy) - 0.5f;
            const float x0f = floorf(ix), y0f = floorf(iy);
            const int   x0 = (int)x0f,    y0 = (int)y0f;
            const float fx = ix - x0f,    fy = iy - y0f;

            const int x1 = x0 + 1, y1 = y0 + 1;
            const float vx0 = (x0 >= 0 && x0 < WH) ? 1.f : 0.f;
            const float vx1 = (x1 >= 0 && x1 < WH) ? 1.f : 0.f;
            const float vy0 = (y0 >= 0 && y0 < WH) ? 1.f : 0.f;
            const float vy1 = (y1 >= 0 && y1 < WH) ? 1.f : 0.f;

            const int cx0 = min(max(x0, 0), WH - 1);
            const int cx1 = min(max(x1, 0), WH - 1);
            const int cy0 = min(max(y0, 0), WH - 1);
            const int cy1 = min(max(y1, 0), WH - 1);

            const int p = sub * 2 + pp;
            s_pw[pi][p * 2 + 0] = make_uint4(
                (uint32_t)(base + cy0 * WH + cx0) << 6,
                __float_as_uint((1.f - fx) * (1.f - fy) * vy0 * vx0 * wat),
                (uint32_t)(base + cy0 * WH + cx1) << 6,
                __float_as_uint(fx * (1.f - fy) * vy0 * vx1 * wat));
            s_pw[pi][p * 2 + 1] = make_uint4(
                (uint32_t)(base + cy1 * WH + cx0) << 6,
                __float_as_uint((1.f - fx) * fy * vy1 * vx0 * wat),
                (uint32_t)(base + cy1 * WH + cx1) << 6,
                __float_as_uint(fx * fy * vy1 * vx1 * wat));
        }
    }
    __syncthreads();

    // ---------- phase 2 ----------
    const int wid  = tid >> 5;
    const int lane = tid & 31;
    const int g    = lane >> 2;    // corner slot 0..7
    const int quad = lane & 3;     // 16-byte quad -> channels quad*8..+7

    #pragma unroll 1
    for (int pp = 0; pp < 4; pp++) {
        const int pi = wid * 4 + pp;
        const int gp = blockIdx.x * GPB + pi;
        const int h  = gp & 7;
        const int bq = gp >> 3;
        const int b  = (bq >= LQ) ? 1 : 0;
        const char* vbc = (const char*)g_value_h
            + ((size_t)(b * NHEADS + h) * LEN_IN) * (HDIM * 2) + quad * 16;
        const char* pwb = (const char*)&s_pw[pi][0] + g * 8;

        float a0 = 0.f, a1 = 0.f, a2 = 0.f, a3 = 0.f, a4 = 0.f, a5 = 0.f, a6 = 0.f, a7 = 0.f;
        #pragma unroll
        for (int t = 0; t < 8; t++) {
            const uint2 pw = *(const uint2*)(pwb + t * 64);
            const float w  = __uint_as_float(pw.y);
            const uint4 v  = *(const uint4*)(vbc + pw.x);
            const float2 f0 = __half22float2(*(const __half2*)&v.x);
            const float2 f1 = __half22float2(*(const __half2*)&v.y);
            const float2 f2 = __half22float2(*(const __half2*)&v.z);
            const float2 f3 = __half22float2(*(const __half2*)&v.w);
            a0 = fmaf(w, f0.x, a0); a1 = fmaf(w, f0.y, a1);
            a2 = fmaf(w, f1.x, a2); a3 = fmaf(w, f1.y, a3);
            a4 = fmaf(w, f2.x, a4); a5 = fmaf(w, f2.y, a5);
            a6 = fmaf(w, f3.x, a6); a7 = fmaf(w, f3.y, a7);
        }
        #pragma unroll
        for (int s = 4; s <= 16; s <<= 1) {
            a0 += __shfl_xor_sync(0xffffffffu, a0, s);
            a1 += __shfl_xor_sync(0xffffffffu, a1, s);
            a2 += __shfl_xor_sync(0xffffffffu, a2, s);
            a3 += __shfl_xor_sync(0xffffffffu, a3, s);
            a4 += __shfl_xor_sync(0xffffffffu, a4, s);
            a5 += __shfl_xor_sync(0xffffffffu, a5, s);
            a6 += __shfl_xor_sync(0xffffffffu, a6, s);
            a7 += __shfl_xor_sync(0xffffffffu, a7, s);
        }
        if (lane < 4) {
            __half2 h0 = __floats2half2_rn(a0, a1);
            __half2 h1 = __floats2half2_rn(a2, a3);
            __half2 h2 = __floats2half2_rn(a4, a5);
            __half2 h3 = __floats2half2_rn(a6, a7);
            uint4 st = make_uint4(*(uint32_t*)&h0, *(uint32_t*)&h1,
                                  *(uint32_t*)&h2, *(uint32_t*)&h3);
            *(uint4*)((char*)g_samp_h + (size_t)bq * (DMODEL * 2) + h * 64 + lane * 16) = st;
        }
    }
}

// ---------------- launch ----------------
extern "C" void kernel_launch(void* const* d_in, const int* in_sizes, int n_in,
                              void* d_out, int out_size)
{
    (void)in_sizes; (void)n_in; (void)out_size;
    const float* query  = (const float*)d_in[0];
    const float* refp   = (const float*)d_in[1];
    const float* xin    = (const float*)d_in[2];
    const float* W_off  = (const float*)d_in[3];
    const float* b_off  = (const float*)d_in[4];
    const float* W_attn = (const float*)d_in[5];
    const float* b_attn = (const float*)d_in[6];
    const float* W_val  = (const float*)d_in[7];
    const float* b_val  = (const float*)d_in[8];
    const float* W_out  = (const float*)d_in[9];
    const float* b_out  = (const float*)d_in[10];
    float* out = (float*)d_out;

    float *p_qproj, *p_bq;
    __half *p_samp_h, *p_Wq_hi, *p_Wq_lo, *p_Wv_hi, *p_Wv_lo, *p_Wo_hi, *p_Wo_lo;
    cudaGetSymbolAddress((void**)&p_qproj,  g_qproj);
    cudaGetSymbolAddress((void**)&p_samp_h, g_samp_h);
    cudaGetSymbolAddress((void**)&p_bq,     g_bq);
    cudaGetSymbolAddress((void**)&p_Wq_hi,  g_Wq_hi);
    cudaGetSymbolAddress((void**)&p_Wq_lo,  g_Wq_lo);
    cudaGetSymbolAddress((void**)&p_Wv_hi,  g_Wv_hi);
    cudaGetSymbolAddress((void**)&p_Wv_lo,  g_Wv_lo);
    cudaGetSymbolAddress((void**)&p_Wo_hi,  g_Wo_hi);
    cudaGetSymbolAddress((void**)&p_Wo_lo,  g_Wo_lo);

    cudaFuncSetAttribute(gemm_hmma<0>, cudaFuncAttributeMaxDynamicSharedMemorySize, SMEM_GEMM);
    cudaFuncSetAttribute(gemm_hmma<1>, cudaFuncAttributeMaxDynamicSharedMemorySize, SMEM_GEMM);
    cudaFuncSetAttribute(gemm_hmma<2>, cudaFuncAttributeMaxDynamicSharedMemorySize, SMEM_GEMM);

    // 0) weight prep
    {
        const int total = KDIM * NQP + 2 * KDIM * DMODEL;
        prep_weights<<<(total + 255) / 256, 256>>>(W_off, b_off, W_attn, b_attn, W_val, W_out);
    }

    const int MB = MROWS / 128;   // 340

    // 1) value projection -> fp16 head-major
    gemm_hmma<1><<<dim3(2, MB), 256, SMEM_GEMM>>>(xin, nullptr, p_Wv_hi, p_Wv_lo, b_val, nullptr, 256);

    // 2) fused query projection (N=384)
    gemm_hmma<0><<<dim3(3, MB), 256, SMEM_GEMM>>>(query, nullptr, p_Wq_hi, p_Wq_lo, p_bq, p_qproj, NQP);

    // 3) block-staged softmax + deformable sampling -> fp16 samp
    deform_sample<<<(MROWS * NHEADS) / GPB, 256>>>(refp);

    // 4) output projection: fp16 A, 2-pass
    gemm_hmma<2><<<dim3(2, MB), 256, SMEM_GEMM>>>(nullptr, p_samp_h, p_Wo_hi, p_Wo_lo, b_out, out, 256);
}

// round 7
// speedup vs baseline: 3.5286x; 1.0920x over previous
#include <cuda_runtime.h>
#include <cuda_fp16.h>
#include <math.h>
#include <stdint.h>

// ---------------- problem constants ----------------
#define BATCH    2
#define LQ       21760
#define LEN_IN   21760
#define DMODEL   256
#define NHEADS   8
#define HDIM     32
#define MROWS    (BATCH*LQ)       // 43520
#define NQP      384              // fused off(256)+attn(128)
#define KDIM     256
#define GPB      32               // (q,h) pairs per sampler block

// level geometry
__device__ __constant__ int c_lvlWH[4]   = {128, 64, 32, 16};
__device__ __constant__ int c_lvlBase[4] = {0, 16384, 20480, 21504};

// ---------------- scratch ----------------
__device__ __align__(16) __half g_value_h[(size_t)BATCH*NHEADS*LEN_IN*HDIM]; // [b][h][pix][32]
__device__ float g_qproj[(size_t)MROWS*NQP];
__device__ __align__(16) __half g_samp_h[(size_t)MROWS*DMODEL];
// fp16 activations (hi only; 2-pass split keeps B accurate)
__device__ __align__(16) __half g_q_h[(size_t)MROWS*KDIM];
__device__ __align__(16) __half g_x_h[(size_t)MROWS*KDIM];
// weights split hi/lo in [k][n] layout
__device__ __half g_Wq_hi[KDIM*NQP],    g_Wq_lo[KDIM*NQP];
__device__ __half g_Wv_hi[KDIM*DMODEL], g_Wv_lo[KDIM*DMODEL];
__device__ __half g_Wo_hi[KDIM*DMODEL], g_Wo_lo[KDIM*DMODEL];
__device__ float g_bq[NQP];

// ---------------- PTX helpers ----------------
__device__ __forceinline__ uint32_t smem_u32(const void* p) {
    uint32_t a;
    asm("{ .reg .u64 t; cvta.to.shared.u64 t, %1; cvt.u32.u64 %0, t; }" : "=r"(a) : "l"(p));
    return a;
}
__device__ __forceinline__ void ldsm4(uint32_t* r, uint32_t a) {
    asm volatile("ldmatrix.sync.aligned.m8n8.x4.shared.b16 {%0,%1,%2,%3}, [%4];"
                 : "=r"(r[0]), "=r"(r[1]), "=r"(r[2]), "=r"(r[3]) : "r"(a));
}
__device__ __forceinline__ void ldsm4t(uint32_t* r, uint32_t a) {
    asm volatile("ldmatrix.sync.aligned.m8n8.x4.trans.shared.b16 {%0,%1,%2,%3}, [%4];"
                 : "=r"(r[0]), "=r"(r[1]), "=r"(r[2]), "=r"(r[3]) : "r"(a));
}
__device__ __forceinline__ void mma16816(float* c, const uint32_t* a, const uint32_t* b) {
    asm volatile("mma.sync.aligned.m16n8k16.row.col.f32.f16.f16.f32 "
                 "{%0,%1,%2,%3}, {%4,%5,%6,%7}, {%8,%9}, {%0,%1,%2,%3};"
                 : "+f"(c[0]), "+f"(c[1]), "+f"(c[2]), "+f"(c[3])
                 : "r"(a[0]), "r"(a[1]), "r"(a[2]), "r"(a[3]), "r"(b[0]), "r"(b[1]));
}
__device__ __forceinline__ void cpa16(uint32_t s, const void* g) {
    asm volatile("cp.async.cg.shared.global [%0], [%1], 16;" :: "r"(s), "l"(g));
}

// ---------------- weight prep: split fp16 hi/lo, [k][n] layout ----------------
__global__ void prep_weights(const float* __restrict__ W_off, const float* __restrict__ b_off,
                             const float* __restrict__ W_attn, const float* __restrict__ b_attn,
                             const float* __restrict__ W_val, const float* __restrict__ W_out)
{
    const int i = blockIdx.x * 256 + threadIdx.x;
    const int NQ = KDIM * NQP;
    const int NV = KDIM * DMODEL;
    float w; __half *ph, *pl; int idx;
    if (i < NQ) {
        int k = i / NQP, n = i % NQP;
        w = (n < 256) ? W_off[k * 256 + n] : W_attn[k * 128 + (n - 256)];
        ph = g_Wq_hi; pl = g_Wq_lo; idx = i;
    } else if (i < NQ + NV) {
        idx = i - NQ;
        w = W_val[idx];
        ph = g_Wv_hi; pl = g_Wv_lo;
    } else if (i < NQ + 2 * NV) {
        idx = i - NQ - NV;
        w = W_out[idx];
        ph = g_Wo_hi; pl = g_Wo_lo;
    } else return;
    __half hi = __float2half_rn(w);
    __half lo = __float2half_rn(w - __half2float(hi));
    ph[idx] = hi; pl[idx] = lo;
    if (i < NQP) g_bq[i] = (i < 256) ? b_off[i] : b_attn[i - 256];
}

// ---------------- activation prep: fp32 -> fp16 (vectorized) ----------------
__global__ void prep_acts(const float* __restrict__ q, const float* __restrict__ x)
{
    const size_t i = ((size_t)blockIdx.x * 256 + threadIdx.x) * 4;
    const float4 v = *(const float4*)(q + i);
    __half2 a0 = __floats2half2_rn(v.x, v.y);
    __half2 a1 = __floats2half2_rn(v.z, v.w);
    *(uint2*)(g_q_h + i) = make_uint2(*(uint32_t*)&a0, *(uint32_t*)&a1);
    const float4 u = *(const float4*)(x + i);
    __half2 b0 = __floats2half2_rn(u.x, u.y);
    __half2 b1 = __floats2half2_rn(u.z, u.w);
    *(uint2*)(g_x_h + i) = make_uint2(*(uint32_t*)&b0, *(uint32_t*)&b1);
}

// ---------------- HMMA 2-pass GEMM with cp.async double buffer ----------------
// C[M,N] = Ah[M,256] * (Wh+Wl)[256,N] + bias.  BM=BN=128 per CTA, 8 warps.
// VOUT: write fp16 head-major value [b][h][pix][32] instead of fp32 C.
#define ASTRIDE 144
#define BSTRIDE 272
#define SOFF_BH 18432                 // 128*144
#define SOFF_BL (18432+17408)         // + 64*272
#define STAGE   (18432+2*17408)       // 53248
#define SMEM_GEMM (2*STAGE)           // 106496

template<bool VOUT>
__global__ __launch_bounds__(256, 2)
void gemm_hmma2(const __half* __restrict__ Ah,
                const __half* __restrict__ Wh, const __half* __restrict__ Wl,
                const float* __restrict__ bias, float* __restrict__ C, int N)
{
    extern __shared__ __align__(16) char dsm[];
    const uint32_t sb = smem_u32(dsm);

    const int tid  = threadIdx.x;
    const int wid  = tid >> 5;
    const int lane = tid & 31;
    const int bm   = blockIdx.y * 128;
    const int bn   = blockIdx.x * 128;
    const int m0   = (wid & 3) * 32;
    const int n0w  = (wid >> 2) * 64;

    float acc[2][8][4];
    #pragma unroll
    for (int i = 0; i < 2; i++)
        #pragma unroll
        for (int j = 0; j < 8; j++)
            #pragma unroll
            for (int q = 0; q < 4; q++) acc[i][j][q] = 0.f;

    // async loader: one K-chunk (A 128x64, B hi/lo 64x128) into stage buf
    auto issue = [&](int c, int buf) {
        const uint32_t st = sb + buf * STAGE;
        #pragma unroll
        for (int it = 0; it < 4; it++) {
            int idx = tid + it * 256;
            int r   = idx >> 3;
            int col = (idx & 7) * 8;
            cpa16(st + r * ASTRIDE + col * 2,
                  Ah + (size_t)(bm + r) * KDIM + c * 64 + col);
        }
        #pragma unroll
        for (int it = 0; it < 8; it++) {
            int idx = tid + it * 256;
            const __half* src = (it < 4) ? Wh : Wl;
            const uint32_t mo = (it < 4) ? 0u : (uint32_t)(SOFF_BL - SOFF_BH);
            int j   = idx & 1023;
            int r   = j >> 4;
            int col = (j & 15) * 8;
            cpa16(st + SOFF_BH + mo + r * BSTRIDE + col * 2,
                  src + (size_t)(c * 64 + r) * N + bn + col);
        }
    };

    const uint32_t aOff = (uint32_t)((m0 + (lane & 15)) * ASTRIDE + (lane >> 4) * 16);
    const uint32_t bOff = (uint32_t)(((lane & 7) + ((lane >> 3) & 1) * 8) * BSTRIDE
                                     + (lane >> 4) * 16 + n0w * 2);

    issue(0, 0);
    asm volatile("cp.async.commit_group;" ::: "memory");

    for (int c = 0; c < 4; c++) {
        if (c < 3) {
            issue(c + 1, (c + 1) & 1);
            asm volatile("cp.async.commit_group;" ::: "memory");
            asm volatile("cp.async.wait_group 1;" ::: "memory");
        } else {
            asm volatile("cp.async.wait_group 0;" ::: "memory");
        }
        __syncthreads();

        const uint32_t st = sb + (c & 1) * STAGE;
        #pragma unroll
        for (int ks = 0; ks < 4; ks++) {
            uint32_t ah[2][4];
            ldsm4(ah[0], st + aOff + ks * 32);
            ldsm4(ah[1], st + aOff + 16 * ASTRIDE + ks * 32);
            #pragma unroll
            for (int hh = 0; hh < 2; hh++) {
                uint32_t bh[8], bl[8];
                const uint32_t bks = bOff + ks * (16 * BSTRIDE) + hh * 64;
                ldsm4t(bh,     st + SOFF_BH + bks);
                ldsm4t(bh + 4, st + SOFF_BH + bks + 32);
                ldsm4t(bl,     st + SOFF_BL + bks);
                ldsm4t(bl + 4, st + SOFF_BL + bks + 32);
                #pragma unroll
                for (int j = 0; j < 4; j++)
                    #pragma unroll
                    for (int i = 0; i < 2; i++)
                        mma16816(acc[i][hh * 4 + j], ah[i], bh + j * 2);
                #pragma unroll
                for (int j = 0; j < 4; j++)
                    #pragma unroll
                    for (int i = 0; i < 2; i++)
                        mma16816(acc[i][hh * 4 + j], ah[i], bl + j * 2);
            }
        }
        __syncthreads();
    }

    // ---- epilogue ----
    if (VOUT) {
        const int bb = (bm >= LEN_IN) ? 1 : 0;
        const int pixbase = bm - bb * LEN_IN;
        #pragma unroll
        for (int i = 0; i < 2; i++) {
            const int pix = pixbase + m0 + i * 16 + (lane >> 2);
            #pragma unroll
            for (int j = 0; j < 8; j++) {
                const int cc = bn + n0w + j * 8 + (lane & 3) * 2;
                const int head = cc >> 5, chp = cc & 31;
                const float2 bv = *(const float2*)(bias + cc);
                __half* dst = g_value_h
                    + ((size_t)(bb * NHEADS + head) * LEN_IN + pix) * HDIM + chp;
                __half2 v0 = __floats2half2_rn(acc[i][j][0] + bv.x, acc[i][j][1] + bv.y);
                __half2 v1 = __floats2half2_rn(acc[i][j][2] + bv.x, acc[i][j][3] + bv.y);
                *(__half2*)dst = v0;
                *(__half2*)(dst + 8 * HDIM) = v1;
            }
        }
    } else {
        #pragma unroll
        for (int i = 0; i < 2; i++) {
            const int r0 = bm + m0 + i * 16 + (lane >> 2);
            #pragma unroll
            for (int j = 0; j < 8; j++) {
                const int cc = bn + n0w + j * 8 + (lane & 3) * 2;
                const float2 bv = *(const float2*)(bias + cc);
                float2 v0 = make_float2(acc[i][j][0] + bv.x, acc[i][j][1] + bv.y);
                float2 v1 = make_float2(acc[i][j][2] + bv.x, acc[i][j][3] + bv.y);
                *(float2*)(C + (size_t)r0 * N + cc) = v0;
                *(float2*)(C + (size_t)(r0 + 8) * N + cc) = v1;
            }
        }
    }
}

// ---------------- block-staged softmax + deformable sampling ----------------
__global__ __launch_bounds__(256)
void deform_sample(const float* __restrict__ refp)
{
    __shared__ uint4 s_pw[GPB][32];

    const int tid = threadIdx.x;

    // ---------- phase 1 ----------
    {
        const int pi  = tid >> 3;
        const int sub = tid & 7;
        const int gp  = blockIdx.x * GPB + pi;
        const int h   = gp & 7;
        const int bq  = gp >> 3;
        const float* row = g_qproj + (size_t)bq * NQP;

        float lg0 = row[256 + h * 16 + 2 * sub];
        float lg1 = row[256 + h * 16 + 2 * sub + 1];
        float mx = fmaxf(lg0, lg1);
        #pragma unroll
        for (int s = 1; s < 8; s <<= 1) mx = fmaxf(mx, __shfl_xor_sync(0xffffffffu, mx, s));
        float e0 = __expf(lg0 - mx), e1 = __expf(lg1 - mx);
        float sm = e0 + e1;
        #pragma unroll
        for (int s = 1; s < 8; s <<= 1) sm += __shfl_xor_sync(0xffffffffu, sm, s);
        const float inv = __frcp_rn(sm);

        const float4 of = *(const float4*)(row + h * 32 + sub * 4);
        const int l = sub >> 1;
        const float2 rf = *(const float2*)(refp + (size_t)bq * 8 + l * 2);

        const int   WH   = c_lvlWH[l];
        const int   base = c_lvlBase[l];
        const float Wf   = (float)WH;

        #pragma unroll
        for (int pp = 0; pp < 2; pp++) {
            const float ox = pp ? of.z : of.x;
            const float oy = pp ? of.w : of.y;
            const float wat = (pp ? e1 : e0) * inv;

            const float ix = fmaf(rf.x, Wf, ox) - 0.5f;
            const float iy = fmaf(rf.y, Wf, oy) - 0.5f;
            const float x0f = floorf(ix), y0f = floorf(iy);
            const int   x0 = (int)x0f,    y0 = (int)y0f;
            const float fx = ix - x0f,    fy = iy - y0f;

            const int x1 = x0 + 1, y1 = y0 + 1;
            const float vx0 = (x0 >= 0 && x0 < WH) ? 1.f : 0.f;
            const float vx1 = (x1 >= 0 && x1 < WH) ? 1.f : 0.f;
            const float vy0 = (y0 >= 0 && y0 < WH) ? 1.f : 0.f;
            const float vy1 = (y1 >= 0 && y1 < WH) ? 1.f : 0.f;

            const int cx0 = min(max(x0, 0), WH - 1);
            const int cx1 = min(max(x1, 0), WH - 1);
            const int cy0 = min(max(y0, 0), WH - 1);
            const int cy1 = min(max(y1, 0), WH - 1);

            const int p = sub * 2 + pp;
            s_pw[pi][p * 2 + 0] = make_uint4(
                (uint32_t)(base + cy0 * WH + cx0) << 6,
                __float_as_uint((1.f - fx) * (1.f - fy) * vy0 * vx0 * wat),
                (uint32_t)(base + cy0 * WH + cx1) << 6,
                __float_as_uint(fx * (1.f - fy) * vy0 * vx1 * wat));
            s_pw[pi][p * 2 + 1] = make_uint4(
                (uint32_t)(base + cy1 * WH + cx0) << 6,
                __float_as_uint((1.f - fx) * fy * vy1 * vx0 * wat),
                (uint32_t)(base + cy1 * WH + cx1) << 6,
                __float_as_uint(fx * fy * vy1 * vx1 * wat));
        }
    }
    __syncthreads();

    // ---------- phase 2 ----------
    const int wid  = tid >> 5;
    const int lane = tid & 31;
    const int g    = lane >> 2;
    const int quad = lane & 3;

    #pragma unroll 1
    for (int pp = 0; pp < 4; pp++) {
        const int pi = wid * 4 + pp;
        const int gp = blockIdx.x * GPB + pi;
        const int h  = gp & 7;
        const int bq = gp >> 3;
        const int b  = (bq >= LQ) ? 1 : 0;
        const char* vbc = (const char*)g_value_h
            + ((size_t)(b * NHEADS + h) * LEN_IN) * (HDIM * 2) + quad * 16;
        const char* pwb = (const char*)&s_pw[pi][0] + g * 8;

        float a0 = 0.f, a1 = 0.f, a2 = 0.f, a3 = 0.f, a4 = 0.f, a5 = 0.f, a6 = 0.f, a7 = 0.f;
        #pragma unroll
        for (int t = 0; t < 8; t++) {
            const uint2 pw = *(const uint2*)(pwb + t * 64);
            const float w  = __uint_as_float(pw.y);
            const uint4 v  = *(const uint4*)(vbc + pw.x);
            const float2 f0 = __half22float2(*(const __half2*)&v.x);
            const float2 f1 = __half22float2(*(const __half2*)&v.y);
            const float2 f2 = __half22float2(*(const __half2*)&v.z);
            const float2 f3 = __half22float2(*(const __half2*)&v.w);
            a0 = fmaf(w, f0.x, a0); a1 = fmaf(w, f0.y, a1);
            a2 = fmaf(w, f1.x, a2); a3 = fmaf(w, f1.y, a3);
            a4 = fmaf(w, f2.x, a4); a5 = fmaf(w, f2.y, a5);
            a6 = fmaf(w, f3.x, a6); a7 = fmaf(w, f3.y, a7);
        }
        #pragma unroll
        for (int s = 4; s <= 16; s <<= 1) {
            a0 += __shfl_xor_sync(0xffffffffu, a0, s);
            a1 += __shfl_xor_sync(0xffffffffu, a1, s);
            a2 += __shfl_xor_sync(0xffffffffu, a2, s);
            a3 += __shfl_xor_sync(0xffffffffu, a3, s);
            a4 += __shfl_xor_sync(0xffffffffu, a4, s);
            a5 += __shfl_xor_sync(0xffffffffu, a5, s);
            a6 += __shfl_xor_sync(0xffffffffu, a6, s);
            a7 += __shfl_xor_sync(0xffffffffu, a7, s);
        }
        if (lane < 4) {
            __half2 h0 = __floats2half2_rn(a0, a1);
            __half2 h1 = __floats2half2_rn(a2, a3);
            __half2 h2 = __floats2half2_rn(a4, a5);
            __half2 h3 = __floats2half2_rn(a6, a7);
            uint4 st = make_uint4(*(uint32_t*)&h0, *(uint32_t*)&h1,
                                  *(uint32_t*)&h2, *(uint32_t*)&h3);
            *(uint4*)((char*)g_samp_h + (size_t)bq * (DMODEL * 2) + h * 64 + lane * 16) = st;
        }
    }
}

// ---------------- launch ----------------
extern "C" void kernel_launch(void* const* d_in, const int* in_sizes, int n_in,
                              void* d_out, int out_size)
{
    (void)in_sizes; (void)n_in; (void)out_size;
    const float* query  = (const float*)d_in[0];
    const float* refp   = (const float*)d_in[1];
    const float* xin    = (const float*)d_in[2];
    const float* W_off  = (const float*)d_in[3];
    const float* b_off  = (const float*)d_in[4];
    const float* W_attn = (const float*)d_in[5];
    const float* b_attn = (const float*)d_in[6];
    const float* W_val  = (const float*)d_in[7];
    const float* b_val  = (const float*)d_in[8];
    const float* W_out  = (const float*)d_in[9];
    const float* b_out  = (const float*)d_in[10];
    float* out = (float*)d_out;

    float *p_qproj, *p_bq;
    __half *p_samp_h, *p_q_h, *p_x_h;
    __half *p_Wq_hi, *p_Wq_lo, *p_Wv_hi, *p_Wv_lo, *p_Wo_hi, *p_Wo_lo;
    cudaGetSymbolAddress((void**)&p_qproj,  g_qproj);
    cudaGetSymbolAddress((void**)&p_samp_h, g_samp_h);
    cudaGetSymbolAddress((void**)&p_q_h,    g_q_h);
    cudaGetSymbolAddress((void**)&p_x_h,    g_x_h);
    cudaGetSymbolAddress((void**)&p_bq,     g_bq);
    cudaGetSymbolAddress((void**)&p_Wq_hi,  g_Wq_hi);
    cudaGetSymbolAddress((void**)&p_Wq_lo,  g_Wq_lo);
    cudaGetSymbolAddress((void**)&p_Wv_hi,  g_Wv_hi);
    cudaGetSymbolAddress((void**)&p_Wv_lo,  g_Wv_lo);
    cudaGetSymbolAddress((void**)&p_Wo_hi,  g_Wo_hi);
    cudaGetSymbolAddress((void**)&p_Wo_lo,  g_Wo_lo);

    cudaFuncSetAttribute(gemm_hmma2<false>, cudaFuncAttributeMaxDynamicSharedMemorySize, SMEM_GEMM);
    cudaFuncSetAttribute(gemm_hmma2<true>,  cudaFuncAttributeMaxDynamicSharedMemorySize, SMEM_GEMM);

    // 0) weight prep + activation fp16 conversion
    {
        const int total = KDIM * NQP + 2 * KDIM * DMODEL;
        prep_weights<<<(total + 255) / 256, 256>>>(W_off, b_off, W_attn, b_attn, W_val, W_out);
        prep_acts<<<(MROWS * KDIM / 4) / 256, 256>>>(query, xin);
    }

    const int MB = MROWS / 128;   // 340

    // 1) value projection -> fp16 head-major
    gemm_hmma2<true><<<dim3(2, MB), 256, SMEM_GEMM>>>(p_x_h, p_Wv_hi, p_Wv_lo, b_val, nullptr, 256);

    // 2) fused query projection (N=384)
    gemm_hmma2<false><<<dim3(3, MB), 256, SMEM_GEMM>>>(p_q_h, p_Wq_hi, p_Wq_lo, p_bq, p_qproj, NQP);

    // 3) block-staged softmax + deformable sampling -> fp16 samp
    deform_sample<<<(MROWS * NHEADS) / GPB, 256>>>(refp);

    // 4) output projection
    gemm_hmma2<false><<<dim3(2, MB), 256, SMEM_GEMM>>>(p_samp_h, p_Wo_hi, p_Wo_lo, b_out, out, 256);
}

// round 8
// speedup vs baseline: 3.6708x; 1.0403x over previous
#include <cuda_runtime.h>
#include <cuda_fp16.h>
#include <math.h>
#include <stdint.h>

// ---------------- problem constants ----------------
#define BATCH    2
#define LQ       21760
#define LEN_IN   21760
#define DMODEL   256
#define NHEADS   8
#define HDIM     32
#define MROWS    (BATCH*LQ)       // 43520
#define NQP      384              // fused off(256)+attn(128)
#define KDIM     256
#define GPB      32               // (q,h) pairs per sampler block

// level geometry
__device__ __constant__ int c_lvlWH[4]   = {128, 64, 32, 16};
__device__ __constant__ int c_lvlBase[4] = {0, 16384, 20480, 21504};

// ---------------- scratch ----------------
__device__ __align__(16) __half g_value_h[(size_t)BATCH*NHEADS*LEN_IN*HDIM]; // [b][h][pix][32]
__device__ float g_qproj[(size_t)MROWS*NQP];
__device__ __align__(16) __half g_samp_h[(size_t)MROWS*DMODEL];
// weights split hi/lo in [k][n] layout
__device__ __half g_Wq_hi[KDIM*NQP],    g_Wq_lo[KDIM*NQP];
__device__ __half g_Wv_hi[KDIM*DMODEL];
__device__ __half g_Wo_hi[KDIM*DMODEL], g_Wo_lo[KDIM*DMODEL];
__device__ float g_bq[NQP];

// ---------------- PTX helpers ----------------
__device__ __forceinline__ uint32_t smem_u32(const void* p) {
    uint32_t a;
    asm("{ .reg .u64 t; cvta.to.shared.u64 t, %1; cvt.u32.u64 %0, t; }" : "=r"(a) : "l"(p));
    return a;
}
__device__ __forceinline__ void ldsm4(uint32_t* r, uint32_t a) {
    asm volatile("ldmatrix.sync.aligned.m8n8.x4.shared.b16 {%0,%1,%2,%3}, [%4];"
                 : "=r"(r[0]), "=r"(r[1]), "=r"(r[2]), "=r"(r[3]) : "r"(a));
}
__device__ __forceinline__ void ldsm4t(uint32_t* r, uint32_t a) {
    asm volatile("ldmatrix.sync.aligned.m8n8.x4.trans.shared.b16 {%0,%1,%2,%3}, [%4];"
                 : "=r"(r[0]), "=r"(r[1]), "=r"(r[2]), "=r"(r[3]) : "r"(a));
}
__device__ __forceinline__ void mma16816(float* c, const uint32_t* a, const uint32_t* b) {
    asm volatile("mma.sync.aligned.m16n8k16.row.col.f32.f16.f16.f32 "
                 "{%0,%1,%2,%3}, {%4,%5,%6,%7}, {%8,%9}, {%0,%1,%2,%3};"
                 : "+f"(c[0]), "+f"(c[1]), "+f"(c[2]), "+f"(c[3])
                 : "r"(a[0]), "r"(a[1]), "r"(a[2]), "r"(a[3]), "r"(b[0]), "r"(b[1]));
}
__device__ __forceinline__ void cpa16(uint32_t s, const void* g) {
    asm volatile("cp.async.cg.shared.global [%0], [%1], 16;" :: "r"(s), "l"(g));
}
__device__ __forceinline__ uint32_t packh(__half a, __half b) {
    __half2 t = __halves2half2(a, b);
    return *(uint32_t*)&t;
}

// ---------------- weight prep ----------------
__global__ void prep_weights(const float* __restrict__ W_off, const float* __restrict__ b_off,
                             const float* __restrict__ W_attn, const float* __restrict__ b_attn,
                             const float* __restrict__ W_val, const float* __restrict__ W_out)
{
    const int i = blockIdx.x * 256 + threadIdx.x;
    const int NQ = KDIM * NQP;
    const int NV = KDIM * DMODEL;
    if (i < NQ) {
        int k = i / NQP, n = i % NQP;
        float w = (n < 256) ? W_off[k * 256 + n] : W_attn[k * 128 + (n - 256)];
        __half hi = __float2half_rn(w);
        g_Wq_hi[i] = hi;
        g_Wq_lo[i] = __float2half_rn(w - __half2float(hi));
    } else if (i < NQ + NV) {
        int idx = i - NQ;
        g_Wv_hi[idx] = __float2half_rn(W_val[idx]);      // value GEMM is 1-pass
    } else if (i < NQ + 2 * NV) {
        int idx = i - NQ - NV;
        float w = W_out[idx];
        __half hi = __float2half_rn(w);
        g_Wo_hi[idx] = hi;
        g_Wo_lo[idx] = __float2half_rn(w - __half2float(hi));
    } else return;
    if (i < NQP) g_bq[i] = (i < 256) ? b_off[i] : b_attn[i - 256];
}

// ---------------- HMMA GEMM ----------------
// AMODE 0: A fp32, converted to fp16 in loader.  AMODE 1: A fp16, cp.async.
// BLO: add the W_lo correction pass.  VOUT: fp16 head-major value epilogue.
#define ASTRIDE 144
#define BSTRIDE 272
#define SOFF_BH 18432
#define SOFF_BL (18432+17408)
#define STAGE   (18432+2*17408)       // 53248
#define SMEM_GEMM (2*STAGE)           // 106496

template<int AMODE, bool BLO, bool VOUT>
__global__ __launch_bounds__(256, 2)
void gemm_hmma(const void* __restrict__ Aptr,
               const __half* __restrict__ Wh, const __half* __restrict__ Wl,
               const float* __restrict__ bias, float* __restrict__ C, int N)
{
    extern __shared__ __align__(16) char dsm[];
    const uint32_t sb = smem_u32(dsm);

    const int tid  = threadIdx.x;
    const int wid  = tid >> 5;
    const int lane = tid & 31;
    const int bm   = blockIdx.y * 128;
    const int bn   = blockIdx.x * 128;
    const int m0   = (wid & 3) * 32;
    const int n0w  = (wid >> 2) * 64;

    float acc[2][8][4];
    #pragma unroll
    for (int i = 0; i < 2; i++)
        #pragma unroll
        for (int j = 0; j < 8; j++)
            #pragma unroll
            for (int q = 0; q < 4; q++) acc[i][j][q] = 0.f;

    auto loadA = [&](int c, int buf) {
        const uint32_t st = sb + buf * STAGE;
        if (AMODE == 1) {
            const __half* Ah = (const __half*)Aptr;
            #pragma unroll
            for (int it = 0; it < 4; it++) {
                int idx = tid + it * 256;
                int r   = idx >> 3;
                int col = (idx & 7) * 8;
                cpa16(st + r * ASTRIDE + col * 2,
                      Ah + (size_t)(bm + r) * KDIM + c * 64 + col);
            }
        } else {
            const float* Af = (const float*)Aptr;
            #pragma unroll
            for (int it = 0; it < 8; it++) {
                int idx = tid + it * 256;
                int r   = idx >> 4;
                int k4  = (idx & 15) * 4;
                float4 a = *(const float4*)(Af + (size_t)(bm + r) * KDIM + c * 64 + k4);
                uint32_t h01 = packh(__float2half_rn(a.x), __float2half_rn(a.y));
                uint32_t h23 = packh(__float2half_rn(a.z), __float2half_rn(a.w));
                asm volatile("st.shared.v2.b32 [%0], {%1, %2};"
                             :: "r"(st + r * ASTRIDE + k4 * 2), "r"(h01), "r"(h23) : "memory");
            }
        }
    };
    auto issueB = [&](int c, int buf) {
        const uint32_t st = sb + buf * STAGE;
        const int nit = BLO ? 8 : 4;
        for (int it = 0; it < nit; it++) {
            int idx = tid + it * 256;
            const __half* src = (it < 4) ? Wh : Wl;
            const uint32_t mo = (it < 4) ? 0u : (uint32_t)(SOFF_BL - SOFF_BH);
            int j   = idx & 1023;
            int r   = j >> 4;
            int col = (j & 15) * 8;
            cpa16(st + SOFF_BH + mo + r * BSTRIDE + col * 2,
                  src + (size_t)(c * 64 + r) * N + bn + col);
        }
    };

    const uint32_t aOff = (uint32_t)((m0 + (lane & 15)) * ASTRIDE + (lane >> 4) * 16);
    const uint32_t bOff = (uint32_t)(((lane & 7) + ((lane >> 3) & 1) * 8) * BSTRIDE
                                     + (lane >> 4) * 16 + n0w * 2);

    // prologue
    loadA(0, 0);
    issueB(0, 0);
    asm volatile("cp.async.commit_group;" ::: "memory");

    for (int c = 0; c < 4; c++) {
        if (c < 3) {
            loadA(c + 1, (c + 1) & 1);
            issueB(c + 1, (c + 1) & 1);
            asm volatile("cp.async.commit_group;" ::: "memory");
            asm volatile("cp.async.wait_group 1;" ::: "memory");
        } else {
            asm volatile("cp.async.wait_group 0;" ::: "memory");
        }
        __syncthreads();

        const uint32_t st = sb + (c & 1) * STAGE;
        #pragma unroll
        for (int ks = 0; ks < 4; ks++) {
            uint32_t ah[2][4];
            ldsm4(ah[0], st + aOff + ks * 32);
            ldsm4(ah[1], st + aOff + 16 * ASTRIDE + ks * 32);
            #pragma unroll
            for (int hh = 0; hh < 2; hh++) {
                const uint32_t bks = bOff + ks * (16 * BSTRIDE) + hh * 64;
                uint32_t bh[8];
                ldsm4t(bh,     st + SOFF_BH + bks);
                ldsm4t(bh + 4, st + SOFF_BH + bks + 32);
                #pragma unroll
                for (int j = 0; j < 4; j++)
                    #pragma unroll
                    for (int i = 0; i < 2; i++)
                        mma16816(acc[i][hh * 4 + j], ah[i], bh + j * 2);
                if (BLO) {
                    uint32_t bl[8];
                    ldsm4t(bl,     st + SOFF_BL + bks);
                    ldsm4t(bl + 4, st + SOFF_BL + bks + 32);
                    #pragma unroll
                    for (int j = 0; j < 4; j++)
                        #pragma unroll
                        for (int i = 0; i < 2; i++)
                            mma16816(acc[i][hh * 4 + j], ah[i], bl + j * 2);
                }
            }
        }
        __syncthreads();
    }

    // ---- epilogue ----
    if (VOUT) {
        const int bb = (bm >= LEN_IN) ? 1 : 0;
        const int pixbase = bm - bb * LEN_IN;
        #pragma unroll
        for (int i = 0; i < 2; i++) {
            const int pix = pixbase + m0 + i * 16 + (lane >> 2);
            #pragma unroll
            for (int j = 0; j < 8; j++) {
                const int cc = bn + n0w + j * 8 + (lane & 3) * 2;
                const int head = cc >> 5, chp = cc & 31;
                const float2 bv = *(const float2*)(bias + cc);
                __half* dst = g_value_h
                    + ((size_t)(bb * NHEADS + head) * LEN_IN + pix) * HDIM + chp;
                __half2 v0 = __floats2half2_rn(acc[i][j][0] + bv.x, acc[i][j][1] + bv.y);
                __half2 v1 = __floats2half2_rn(acc[i][j][2] + bv.x, acc[i][j][3] + bv.y);
                *(__half2*)dst = v0;
                *(__half2*)(dst + 8 * HDIM) = v1;
            }
        }
    } else {
        #pragma unroll
        for (int i = 0; i < 2; i++) {
            const int r0 = bm + m0 + i * 16 + (lane >> 2);
            #pragma unroll
            for (int j = 0; j < 8; j++) {
                const int cc = bn + n0w + j * 8 + (lane & 3) * 2;
                const float2 bv = *(const float2*)(bias + cc);
                float2 v0 = make_float2(acc[i][j][0] + bv.x, acc[i][j][1] + bv.y);
                float2 v1 = make_float2(acc[i][j][2] + bv.x, acc[i][j][3] + bv.y);
                *(float2*)(C + (size_t)r0 * N + cc) = v0;
                *(float2*)(C + (size_t)(r0 + 8) * N + cc) = v1;
            }
        }
    }
}

// ---------------- block-staged softmax + deformable sampling ----------------
__global__ __launch_bounds__(256)
void deform_sample(const float* __restrict__ refp)
{
    __shared__ uint4 s_pw[GPB][32];

    const int tid = threadIdx.x;

    // ---------- phase 1 ----------
    {
        const int pi  = tid >> 3;
        const int sub = tid & 7;
        const int gp  = blockIdx.x * GPB + pi;
        const int h   = gp & 7;
        const int bq  = gp >> 3;
        const float* row = g_qproj + (size_t)bq * NQP;

        float lg0 = row[256 + h * 16 + 2 * sub];
        float lg1 = row[256 + h * 16 + 2 * sub + 1];
        float mx = fmaxf(lg0, lg1);
        #pragma unroll
        for (int s = 1; s < 8; s <<= 1) mx = fmaxf(mx, __shfl_xor_sync(0xffffffffu, mx, s));
        float e0 = __expf(lg0 - mx), e1 = __expf(lg1 - mx);
        float sm = e0 + e1;
        #pragma unroll
        for (int s = 1; s < 8; s <<= 1) sm += __shfl_xor_sync(0xffffffffu, sm, s);
        const float inv = __frcp_rn(sm);

        const float4 of = *(const float4*)(row + h * 32 + sub * 4);
        const int l = sub >> 1;
        const float2 rf = *(const float2*)(refp + (size_t)bq * 8 + l * 2);

        const int   WH   = c_lvlWH[l];
        const int   base = c_lvlBase[l];
        const float Wf   = (float)WH;

        #pragma unroll
        for (int pp = 0; pp < 2; pp++) {
            const float ox = pp ? of.z : of.x;
            const float oy = pp ? of.w : of.y;
            const float wat = (pp ? e1 : e0) * inv;

            const float ix = fmaf(rf.x, Wf, ox) - 0.5f;
            const float iy = fmaf(rf.y, Wf, oy) - 0.5f;
            const float x0f = floorf(ix), y0f = floorf(iy);
            const int   x0 = (int)x0f,    y0 = (int)y0f;
            const float fx = ix - x0f,    fy = iy - y0f;

            const int x1 = x0 + 1, y1 = y0 + 1;
            const float vx0 = (x0 >= 0 && x0 < WH) ? 1.f : 0.f;
            const float vx1 = (x1 >= 0 && x1 < WH) ? 1.f : 0.f;
            const float vy0 = (y0 >= 0 && y0 < WH) ? 1.f : 0.f;
            const float vy1 = (y1 >= 0 && y1 < WH) ? 1.f : 0.f;

            const int cx0 = min(max(x0, 0), WH - 1);
            const int cx1 = min(max(x1, 0), WH - 1);
            const int cy0 = min(max(y0, 0), WH - 1);
            const int cy1 = min(max(y1, 0), WH - 1);

            const int p = sub * 2 + pp;
            s_pw[pi][p * 2 + 0] = make_uint4(
                (uint32_t)(base + cy0 * WH + cx0) << 6,
                __float_as_uint((1.f - fx) * (1.f - fy) * vy0 * vx0 * wat),
                (uint32_t)(base + cy0 * WH + cx1) << 6,
                __float_as_uint(fx * (1.f - fy) * vy0 * vx1 * wat));
            s_pw[pi][p * 2 + 1] = make_uint4(
                (uint32_t)(base + cy1 * WH + cx0) << 6,
                __float_as_uint((1.f - fx) * fy * vy1 * vx0 * wat),
                (uint32_t)(base + cy1 * WH + cx1) << 6,
                __float_as_uint(fx * fy * vy1 * vx1 * wat));
        }
    }
    __syncthreads();

    // ---------- phase 2 ----------
    const int wid  = tid >> 5;
    const int lane = tid & 31;
    const int g    = lane >> 2;
    const int quad = lane & 3;

    #pragma unroll 1
    for (int pp = 0; pp < 4; pp++) {
        const int pi = wid * 4 + pp;
        const int gp = blockIdx.x * GPB + pi;
        const int h  = gp & 7;
        const int bq = gp >> 3;
        const int b  = (bq >= LQ) ? 1 : 0;
        const char* vbc = (const char*)g_value_h
            + ((size_t)(b * NHEADS + h) * LEN_IN) * (HDIM * 2) + quad * 16;
        const char* pwb = (const char*)&s_pw[pi][0] + g * 8;

        float a0 = 0.f, a1 = 0.f, a2 = 0.f, a3 = 0.f, a4 = 0.f, a5 = 0.f, a6 = 0.f, a7 = 0.f;
        #pragma unroll
        for (int t = 0; t < 8; t++) {
            const uint2 pw = *(const uint2*)(pwb + t * 64);
            const float w  = __uint_as_float(pw.y);
            const uint4 v  = *(const uint4*)(vbc + pw.x);
            const float2 f0 = __half22float2(*(const __half2*)&v.x);
            const float2 f1 = __half22float2(*(const __half2*)&v.y);
            const float2 f2 = __half22float2(*(const __half2*)&v.z);
            const float2 f3 = __half22float2(*(const __half2*)&v.w);
            a0 = fmaf(w, f0.x, a0); a1 = fmaf(w, f0.y, a1);
            a2 = fmaf(w, f1.x, a2); a3 = fmaf(w, f1.y, a3);
            a4 = fmaf(w, f2.x, a4); a5 = fmaf(w, f2.y, a5);
            a6 = fmaf(w, f3.x, a6); a7 = fmaf(w, f3.y, a7);
        }
        #pragma unroll
        for (int s = 4; s <= 16; s <<= 1) {
            a0 += __shfl_xor_sync(0xffffffffu, a0, s);
            a1 += __shfl_xor_sync(0xffffffffu, a1, s);
            a2 += __shfl_xor_sync(0xffffffffu, a2, s);
            a3 += __shfl_xor_sync(0xffffffffu, a3, s);
            a4 += __shfl_xor_sync(0xffffffffu, a4, s);
            a5 += __shfl_xor_sync(0xffffffffu, a5, s);
            a6 += __shfl_xor_sync(0xffffffffu, a6, s);
            a7 += __shfl_xor_sync(0xffffffffu, a7, s);
        }
        if (lane < 4) {
            __half2 h0 = __floats2half2_rn(a0, a1);
            __half2 h1 = __floats2half2_rn(a2, a3);
            __half2 h2 = __floats2half2_rn(a4, a5);
            __half2 h3 = __floats2half2_rn(a6, a7);
            uint4 st = make_uint4(*(uint32_t*)&h0, *(uint32_t*)&h1,
                                  *(uint32_t*)&h2, *(uint32_t*)&h3);
            *(uint4*)((char*)g_samp_h + (size_t)bq * (DMODEL * 2) + h * 64 + lane * 16) = st;
        }
    }
}

// ---------------- launch ----------------
extern "C" void kernel_launch(void* const* d_in, const int* in_sizes, int n_in,
                              void* d_out, int out_size)
{
    (void)in_sizes; (void)n_in; (void)out_size;
    const float* query  = (const float*)d_in[0];
    const float* refp   = (const float*)d_in[1];
    const float* xin    = (const float*)d_in[2];
    const float* W_off  = (const float*)d_in[3];
    const float* b_off  = (const float*)d_in[4];
    const float* W_attn = (const float*)d_in[5];
    const float* b_attn = (const float*)d_in[6];
    const float* W_val  = (const float*)d_in[7];
    const float* b_val  = (const float*)d_in[8];
    const float* W_out  = (const float*)d_in[9];
    const float* b_out  = (const float*)d_in[10];
    float* out = (float*)d_out;

    float *p_qproj, *p_bq;
    __half *p_samp_h, *p_Wq_hi, *p_Wq_lo, *p_Wv_hi, *p_Wo_hi, *p_Wo_lo;
    cudaGetSymbolAddress((void**)&p_qproj,  g_qproj);
    cudaGetSymbolAddress((void**)&p_samp_h, g_samp_h);
    cudaGetSymbolAddress((void**)&p_bq,     g_bq);
    cudaGetSymbolAddress((void**)&p_Wq_hi,  g_Wq_hi);
    cudaGetSymbolAddress((void**)&p_Wq_lo,  g_Wq_lo);
    cudaGetSymbolAddress((void**)&p_Wv_hi,  g_Wv_hi);
    cudaGetSymbolAddress((void**)&p_Wo_hi,  g_Wo_hi);
    cudaGetSymbolAddress((void**)&p_Wo_lo,  g_Wo_lo);

    cudaFuncSetAttribute(gemm_hmma<0, false, true>,  cudaFuncAttributeMaxDynamicSharedMemorySize, SMEM_GEMM);
    cudaFuncSetAttribute(gemm_hmma<0, true,  false>, cudaFuncAttributeMaxDynamicSharedMemorySize, SMEM_GEMM);
    cudaFuncSetAttribute(gemm_hmma<1, true,  false>, cudaFuncAttributeMaxDynamicSharedMemorySize, SMEM_GEMM);

    // 0) weight prep
    {
        const int total = KDIM * NQP + 2 * KDIM * DMODEL;
        prep_weights<<<(total + 255) / 256, 256>>>(W_off, b_off, W_attn, b_attn, W_val, W_out);
    }

    const int MB = MROWS / 128;   // 340

    // 1) value projection: fp32 A (inline cvt), 1-pass, fp16 head-major out
    gemm_hmma<0, false, true><<<dim3(2, MB), 256, SMEM_GEMM>>>(
        xin, p_Wv_hi, nullptr, b_val, nullptr, 256);

    // 2) fused query projection (N=384): fp32 A, 2-pass
    gemm_hmma<0, true, false><<<dim3(3, MB), 256, SMEM_GEMM>>>(
        query, p_Wq_hi, p_Wq_lo, p_bq, p_qproj, NQP);

    // 3) block-staged softmax + deformable sampling -> fp16 samp
    deform_sample<<<(MROWS * NHEADS) / GPB, 256>>>(refp);

    // 4) output projection: fp16 A (exact), 2-pass
    gemm_hmma<1, true, false><<<dim3(2, MB), 256, SMEM_GEMM>>>(
        p_samp_h, p_Wo_hi, p_Wo_lo, b_out, out, 256);
}

// round 9
// speedup vs baseline: 3.8201x; 1.0407x over previous
#include <cuda_runtime.h>
#include <cuda_fp16.h>
#include <math.h>
#include <stdint.h>

// ---------------- problem constants ----------------
#define BATCH    2
#define LQ       21760
#define LEN_IN   21760
#define DMODEL   256
#define NHEADS   8
#define HDIM     32
#define MROWS    (BATCH*LQ)       // 43520
#define NQP      384              // fused off(256)+attn(128)
#define KDIM     256
#define GPB      32               // (q,h) pairs per sampler block

// level geometry
__device__ __constant__ int c_lvlWH[4]   = {128, 64, 32, 16};
__device__ __constant__ int c_lvlBase[4] = {0, 16384, 20480, 21504};

// ---------------- scratch ----------------
__device__ __align__(16) __half g_value_h[(size_t)BATCH*NHEADS*LEN_IN*HDIM]; // [b][h][pix][32]
__device__ float g_qproj[(size_t)MROWS*NQP];
__device__ __align__(16) __half g_samp_h[(size_t)MROWS*DMODEL];
// weights in [k][n] layout
__device__ __half g_Wq_hi[KDIM*NQP];                       // qproj: 1-pass
__device__ __half g_Wv_hi[KDIM*DMODEL];                    // value: 1-pass
__device__ __half g_Wo_hi[KDIM*DMODEL], g_Wo_lo[KDIM*DMODEL];  // out: 2-pass
__device__ float g_bq[NQP];

// ---------------- PTX helpers ----------------
__device__ __forceinline__ uint32_t smem_u32(const void* p) {
    uint32_t a;
    asm("{ .reg .u64 t; cvta.to.shared.u64 t, %1; cvt.u32.u64 %0, t; }" : "=r"(a) : "l"(p));
    return a;
}
__device__ __forceinline__ void ldsm4(uint32_t* r, uint32_t a) {
    asm volatile("ldmatrix.sync.aligned.m8n8.x4.shared.b16 {%0,%1,%2,%3}, [%4];"
                 : "=r"(r[0]), "=r"(r[1]), "=r"(r[2]), "=r"(r[3]) : "r"(a));
}
__device__ __forceinline__ void ldsm4t(uint32_t* r, uint32_t a) {
    asm volatile("ldmatrix.sync.aligned.m8n8.x4.trans.shared.b16 {%0,%1,%2,%3}, [%4];"
                 : "=r"(r[0]), "=r"(r[1]), "=r"(r[2]), "=r"(r[3]) : "r"(a));
}
__device__ __forceinline__ void mma16816(float* c, const uint32_t* a, const uint32_t* b) {
    asm volatile("mma.sync.aligned.m16n8k16.row.col.f32.f16.f16.f32 "
                 "{%0,%1,%2,%3}, {%4,%5,%6,%7}, {%8,%9}, {%0,%1,%2,%3};"
                 : "+f"(c[0]), "+f"(c[1]), "+f"(c[2]), "+f"(c[3])
                 : "r"(a[0]), "r"(a[1]), "r"(a[2]), "r"(a[3]), "r"(b[0]), "r"(b[1]));
}
__device__ __forceinline__ void cpa16(uint32_t s, const void* g) {
    asm volatile("cp.async.cg.shared.global [%0], [%1], 16;" :: "r"(s), "l"(g));
}
__device__ __forceinline__ uint32_t packh(__half a, __half b) {
    __half2 t = __halves2half2(a, b);
    return *(uint32_t*)&t;
}

// ---------------- weight prep ----------------
__global__ void prep_weights(const float* __restrict__ W_off, const float* __restrict__ b_off,
                             const float* __restrict__ W_attn, const float* __restrict__ b_attn,
                             const float* __restrict__ W_val, const float* __restrict__ W_out)
{
    const int i = blockIdx.x * 256 + threadIdx.x;
    const int NQ = KDIM * NQP;
    const int NV = KDIM * DMODEL;
    if (i < NQ) {
        int k = i / NQP, n = i % NQP;
        float w = (n < 256) ? W_off[k * 256 + n] : W_attn[k * 128 + (n - 256)];
        g_Wq_hi[i] = __float2half_rn(w);
    } else if (i < NQ + NV) {
        int idx = i - NQ;
        g_Wv_hi[idx] = __float2half_rn(W_val[idx]);
    } else if (i < NQ + 2 * NV) {
        int idx = i - NQ - NV;
        float w = W_out[idx];
        __half hi = __float2half_rn(w);
        g_Wo_hi[idx] = hi;
        g_Wo_lo[idx] = __float2half_rn(w - __half2float(hi));
    } else return;
    if (i < NQP) g_bq[i] = (i < 256) ? b_off[i] : b_attn[i - 256];
}

// ---------------- HMMA GEMM ----------------
// AMODE 0: A fp32, converted to fp16 in loader.  AMODE 1: A fp16, cp.async.
// BLO: add the W_lo correction pass.  VOUT: fp16 head-major value epilogue.
#define ASTRIDE 144
#define BSTRIDE 272
#define SOFF_BH 18432
#define SOFF_BL (18432+17408)
#define STAGE   (18432+2*17408)       // 53248
#define SMEM_GEMM (2*STAGE)           // 106496

template<int AMODE, bool BLO, bool VOUT>
__global__ __launch_bounds__(256, 2)
void gemm_hmma(const void* __restrict__ Aptr,
               const __half* __restrict__ Wh, const __half* __restrict__ Wl,
               const float* __restrict__ bias, float* __restrict__ C, int N)
{
    extern __shared__ __align__(16) char dsm[];
    const uint32_t sb = smem_u32(dsm);

    const int tid  = threadIdx.x;
    const int wid  = tid >> 5;
    const int lane = tid & 31;
    const int bm   = blockIdx.y * 128;
    const int bn   = blockIdx.x * 128;
    const int m0   = (wid & 3) * 32;
    const int n0w  = (wid >> 2) * 64;

    float acc[2][8][4];
    #pragma unroll
    for (int i = 0; i < 2; i++)
        #pragma unroll
        for (int j = 0; j < 8; j++)
            #pragma unroll
            for (int q = 0; q < 4; q++) acc[i][j][q] = 0.f;

    auto loadA = [&](int c, int buf) {
        const uint32_t st = sb + buf * STAGE;
        if (AMODE == 1) {
            const __half* Ah = (const __half*)Aptr;
            #pragma unroll
            for (int it = 0; it < 4; it++) {
                int idx = tid + it * 256;
                int r   = idx >> 3;
                int col = (idx & 7) * 8;
                cpa16(st + r * ASTRIDE + col * 2,
                      Ah + (size_t)(bm + r) * KDIM + c * 64 + col);
            }
        } else {
            const float* Af = (const float*)Aptr;
            #pragma unroll
            for (int it = 0; it < 8; it++) {
                int idx = tid + it * 256;
                int r   = idx >> 4;
                int k4  = (idx & 15) * 4;
                float4 a = *(const float4*)(Af + (size_t)(bm + r) * KDIM + c * 64 + k4);
                uint32_t h01 = packh(__float2half_rn(a.x), __float2half_rn(a.y));
                uint32_t h23 = packh(__float2half_rn(a.z), __float2half_rn(a.w));
                asm volatile("st.shared.v2.b32 [%0], {%1, %2};"
                             :: "r"(st + r * ASTRIDE + k4 * 2), "r"(h01), "r"(h23) : "memory");
            }
        }
    };
    auto issueB = [&](int c, int buf) {
        const uint32_t st = sb + buf * STAGE;
        const int nit = BLO ? 8 : 4;
        for (int it = 0; it < nit; it++) {
            int idx = tid + it * 256;
            const __half* src = (it < 4) ? Wh : Wl;
            const uint32_t mo = (it < 4) ? 0u : (uint32_t)(SOFF_BL - SOFF_BH);
            int j   = idx & 1023;
            int r   = j >> 4;
            int col = (j & 15) * 8;
            cpa16(st + SOFF_BH + mo + r * BSTRIDE + col * 2,
                  src + (size_t)(c * 64 + r) * N + bn + col);
        }
    };

    const uint32_t aOff = (uint32_t)((m0 + (lane & 15)) * ASTRIDE + (lane >> 4) * 16);
    const uint32_t bOff = (uint32_t)(((lane & 7) + ((lane >> 3) & 1) * 8) * BSTRIDE
                                     + (lane >> 4) * 16 + n0w * 2);

    // prologue
    loadA(0, 0);
    issueB(0, 0);
    asm volatile("cp.async.commit_group;" ::: "memory");

    for (int c = 0; c < 4; c++) {
        if (c < 3) {
            loadA(c + 1, (c + 1) & 1);
            issueB(c + 1, (c + 1) & 1);
            asm volatile("cp.async.commit_group;" ::: "memory");
            asm volatile("cp.async.wait_group 1;" ::: "memory");
        } else {
            asm volatile("cp.async.wait_group 0;" ::: "memory");
        }
        __syncthreads();

        const uint32_t st = sb + (c & 1) * STAGE;
        #pragma unroll
        for (int ks = 0; ks < 4; ks++) {
            uint32_t ah[2][4];
            ldsm4(ah[0], st + aOff + ks * 32);
            ldsm4(ah[1], st + aOff + 16 * ASTRIDE + ks * 32);
            #pragma unroll
            for (int hh = 0; hh < 2; hh++) {
                const uint32_t bks = bOff + ks * (16 * BSTRIDE) + hh * 64;
                uint32_t bh[8];
                ldsm4t(bh,     st + SOFF_BH + bks);
                ldsm4t(bh + 4, st + SOFF_BH + bks + 32);
                #pragma unroll
                for (int j = 0; j < 4; j++)
                    #pragma unroll
                    for (int i = 0; i < 2; i++)
                        mma16816(acc[i][hh * 4 + j], ah[i], bh + j * 2);
                if (BLO) {
                    uint32_t bl[8];
                    ldsm4t(bl,     st + SOFF_BL + bks);
                    ldsm4t(bl + 4, st + SOFF_BL + bks + 32);
                    #pragma unroll
                    for (int j = 0; j < 4; j++)
                        #pragma unroll
                        for (int i = 0; i < 2; i++)
                            mma16816(acc[i][hh * 4 + j], ah[i], bl + j * 2);
                }
            }
        }
        __syncthreads();
    }

    // ---- epilogue ----
    if (VOUT) {
        const int bb = (bm >= LEN_IN) ? 1 : 0;
        const int pixbase = bm - bb * LEN_IN;
        #pragma unroll
        for (int i = 0; i < 2; i++) {
            const int pix = pixbase + m0 + i * 16 + (lane >> 2);
            #pragma unroll
            for (int j = 0; j < 8; j++) {
                const int cc = bn + n0w + j * 8 + (lane & 3) * 2;
                const int head = cc >> 5, chp = cc & 31;
                const float2 bv = *(const float2*)(bias + cc);
                __half* dst = g_value_h
                    + ((size_t)(bb * NHEADS + head) * LEN_IN + pix) * HDIM + chp;
                __half2 v0 = __floats2half2_rn(acc[i][j][0] + bv.x, acc[i][j][1] + bv.y);
                __half2 v1 = __floats2half2_rn(acc[i][j][2] + bv.x, acc[i][j][3] + bv.y);
                *(__half2*)dst = v0;
                *(__half2*)(dst + 8 * HDIM) = v1;
            }
        }
    } else {
        #pragma unroll
        for (int i = 0; i < 2; i++) {
            const int r0 = bm + m0 + i * 16 + (lane >> 2);
            #pragma unroll
            for (int j = 0; j < 8; j++) {
                const int cc = bn + n0w + j * 8 + (lane & 3) * 2;
                const float2 bv = *(const float2*)(bias + cc);
                float2 v0 = make_float2(acc[i][j][0] + bv.x, acc[i][j][1] + bv.y);
                float2 v1 = make_float2(acc[i][j][2] + bv.x, acc[i][j][3] + bv.y);
                *(float2*)(C + (size_t)r0 * N + cc) = v0;
                *(float2*)(C + (size_t)(r0 + 8) * N + cc) = v1;
            }
        }
    }
}

// ---------------- block-staged softmax + deformable sampling ----------------
__global__ __launch_bounds__(256)
void deform_sample(const float* __restrict__ refp)
{
    __shared__ uint4 s_pw[GPB][32];

    const int tid = threadIdx.x;

    // ---------- phase 1 ----------
    {
        const int pi  = tid >> 3;
        const int sub = tid & 7;
        const int gp  = blockIdx.x * GPB + pi;
        const int h   = gp & 7;
        const int bq  = gp >> 3;
        const float* row = g_qproj + (size_t)bq * NQP;

        float lg0 = row[256 + h * 16 + 2 * sub];
        float lg1 = row[256 + h * 16 + 2 * sub + 1];
        float mx = fmaxf(lg0, lg1);
        #pragma unroll
        for (int s = 1; s < 8; s <<= 1) mx = fmaxf(mx, __shfl_xor_sync(0xffffffffu, mx, s));
        float e0 = __expf(lg0 - mx), e1 = __expf(lg1 - mx);
        float sm = e0 + e1;
        #pragma unroll
        for (int s = 1; s < 8; s <<= 1) sm += __shfl_xor_sync(0xffffffffu, sm, s);
        const float inv = __frcp_rn(sm);

        const float4 of = *(const float4*)(row + h * 32 + sub * 4);
        const int l = sub >> 1;
        const float2 rf = *(const float2*)(refp + (size_t)bq * 8 + l * 2);

        const int   WH   = c_lvlWH[l];
        const int   base = c_lvlBase[l];
        const float Wf   = (float)WH;

        #pragma unroll
        for (int pp = 0; pp < 2; pp++) {
            const float ox = pp ? of.z : of.x;
            const float oy = pp ? of.w : of.y;
            const float wat = (pp ? e1 : e0) * inv;

            const float ix = fmaf(rf.x, Wf, ox) - 0.5f;
            const float iy = fmaf(rf.y, Wf, oy) - 0.5f;
            const float x0f = floorf(ix), y0f = floorf(iy);
            const int   x0 = (int)x0f,    y0 = (int)y0f;
            const float fx = ix - x0f,    fy = iy - y0f;

            const int x1 = x0 + 1, y1 = y0 + 1;
            const float vx0 = (x0 >= 0 && x0 < WH) ? 1.f : 0.f;
            const float vx1 = (x1 >= 0 && x1 < WH) ? 1.f : 0.f;
            const float vy0 = (y0 >= 0 && y0 < WH) ? 1.f : 0.f;
            const float vy1 = (y1 >= 0 && y1 < WH) ? 1.f : 0.f;

            const int cx0 = min(max(x0, 0), WH - 1);
            const int cx1 = min(max(x1, 0), WH - 1);
            const int cy0 = min(max(y0, 0), WH - 1);
            const int cy1 = min(max(y1, 0), WH - 1);

            const int p = sub * 2 + pp;
            s_pw[pi][p * 2 + 0] = make_uint4(
                (uint32_t)(base + cy0 * WH + cx0) << 6,
                __float_as_uint((1.f - fx) * (1.f - fy) * vy0 * vx0 * wat),
                (uint32_t)(base + cy0 * WH + cx1) << 6,
                __float_as_uint(fx * (1.f - fy) * vy0 * vx1 * wat));
            s_pw[pi][p * 2 + 1] = make_uint4(
                (uint32_t)(base + cy1 * WH + cx0) << 6,
                __float_as_uint((1.f - fx) * fy * vy1 * vx0 * wat),
                (uint32_t)(base + cy1 * WH + cx1) << 6,
                __float_as_uint(fx * fy * vy1 * vx1 * wat));
        }
    }
    __syncthreads();

    // ---------- phase 2 ----------
    const int wid  = tid >> 5;
    const int lane = tid & 31;
    const int g    = lane >> 2;
    const int quad = lane & 3;

    #pragma unroll 1
    for (int pp = 0; pp < 4; pp++) {
        const int pi = wid * 4 + pp;
        const int gp = blockIdx.x * GPB + pi;
        const int h  = gp & 7;
        const int bq = gp >> 3;
        const int b  = (bq >= LQ) ? 1 : 0;
        const char* vbc = (const char*)g_value_h
            + ((size_t)(b * NHEADS + h) * LEN_IN) * (HDIM * 2) + quad * 16;
        const char* pwb = (const char*)&s_pw[pi][0] + g * 8;

        float a0 = 0.f, a1 = 0.f, a2 = 0.f, a3 = 0.f, a4 = 0.f, a5 = 0.f, a6 = 0.f, a7 = 0.f;
        #pragma unroll
        for (int t = 0; t < 8; t++) {
            const uint2 pw = *(const uint2*)(pwb + t * 64);
            const float w  = __uint_as_float(pw.y);
            const uint4 v  = *(const uint4*)(vbc + pw.x);
            const float2 f0 = __half22float2(*(const __half2*)&v.x);
            const float2 f1 = __half22float2(*(const __half2*)&v.y);
            const float2 f2 = __half22float2(*(const __half2*)&v.z);
            const float2 f3 = __half22float2(*(const __half2*)&v.w);
            a0 = fmaf(w, f0.x, a0); a1 = fmaf(w, f0.y, a1);
            a2 = fmaf(w, f1.x, a2); a3 = fmaf(w, f1.y, a3);
            a4 = fmaf(w, f2.x, a4); a5 = fmaf(w, f2.y, a5);
            a6 = fmaf(w, f3.x, a6); a7 = fmaf(w, f3.y, a7);
        }
        #pragma unroll
        for (int s = 4; s <= 16; s <<= 1) {
            a0 += __shfl_xor_sync(0xffffffffu, a0, s);
            a1 += __shfl_xor_sync(0xffffffffu, a1, s);
            a2 += __shfl_xor_sync(0xffffffffu, a2, s);
            a3 += __shfl_xor_sync(0xffffffffu, a3, s);
            a4 += __shfl_xor_sync(0xffffffffu, a4, s);
            a5 += __shfl_xor_sync(0xffffffffu, a5, s);
            a6 += __shfl_xor_sync(0xffffffffu, a6, s);
            a7 += __shfl_xor_sync(0xffffffffu, a7, s);
        }
        if (lane < 4) {
            __half2 h0 = __floats2half2_rn(a0, a1);
            __half2 h1 = __floats2half2_rn(a2, a3);
            __half2 h2 = __floats2half2_rn(a4, a5);
            __half2 h3 = __floats2half2_rn(a6, a7);
            uint4 st = make_uint4(*(uint32_t*)&h0, *(uint32_t*)&h1,
                                  *(uint32_t*)&h2, *(uint32_t*)&h3);
            *(uint4*)((char*)g_samp_h + (size_t)bq * (DMODEL * 2) + h * 64 + lane * 16) = st;
        }
    }
}

// ---------------- launch ----------------
extern "C" void kernel_launch(void* const* d_in, const int* in_sizes, int n_in,
                              void* d_out, int out_size)
{
    (void)in_sizes; (void)n_in; (void)out_size;
    const float* query  = (const float*)d_in[0];
    const float* refp   = (const float*)d_in[1];
    const float* xin    = (const float*)d_in[2];
    const float* W_off  = (const float*)d_in[3];
    const float* b_off  = (const float*)d_in[4];
    const float* W_attn = (const float*)d_in[5];
    const float* b_attn = (const float*)d_in[6];
    const float* W_val  = (const float*)d_in[7];
    const float* b_val  = (const float*)d_in[8];
    const float* W_out  = (const float*)d_in[9];
    const float* b_out  = (const float*)d_in[10];
    float* out = (float*)d_out;

    float *p_qproj, *p_bq;
    __half *p_samp_h, *p_Wq_hi, *p_Wv_hi, *p_Wo_hi, *p_Wo_lo;
    cudaGetSymbolAddress((void**)&p_qproj,  g_qproj);
    cudaGetSymbolAddress((void**)&p_samp_h, g_samp_h);
    cudaGetSymbolAddress((void**)&p_bq,     g_bq);
    cudaGetSymbolAddress((void**)&p_Wq_hi,  g_Wq_hi);
    cudaGetSymbolAddress((void**)&p_Wv_hi,  g_Wv_hi);
    cudaGetSymbolAddress((void**)&p_Wo_hi,  g_Wo_hi);
    cudaGetSymbolAddress((void**)&p_Wo_lo,  g_Wo_lo);

    cudaFuncSetAttribute(gemm_hmma<0, false, true>,  cudaFuncAttributeMaxDynamicSharedMemorySize, SMEM_GEMM);
    cudaFuncSetAttribute(gemm_hmma<0, false, false>, cudaFuncAttributeMaxDynamicSharedMemorySize, SMEM_GEMM);
    cudaFuncSetAttribute(gemm_hmma<1, true,  false>, cudaFuncAttributeMaxDynamicSharedMemorySize, SMEM_GEMM);

    // 0) weight prep
    {
        const int total = KDIM * NQP + 2 * KDIM * DMODEL;
        prep_weights<<<(total + 255) / 256, 256>>>(W_off, b_off, W_attn, b_attn, W_val, W_out);
    }

    const int MB = MROWS / 128;   // 340

    // 1) value projection: fp32 A (inline cvt), 1-pass, fp16 head-major out
    gemm_hmma<0, false, true><<<dim3(2, MB), 256, SMEM_GEMM>>>(
        xin, p_Wv_hi, nullptr, b_val, nullptr, 256);

    // 2) fused query projection (N=384): fp32 A, 1-pass
    gemm_hmma<0, false, false><<<dim3(3, MB), 256, SMEM_GEMM>>>(
        query, p_Wq_hi, nullptr, p_bq, p_qproj, NQP);

    // 3) block-staged softmax + deformable sampling -> fp16 samp
    deform_sample<<<(MROWS * NHEADS) / GPB, 256>>>(refp);

    // 4) output projection: fp16 A (exact), 2-pass
    gemm_hmma<1, true, false><<<dim3(2, MB), 256, SMEM_GEMM>>>(
        p_samp_h, p_Wo_hi, p_Wo_lo, b_out, out, 256);
}

// round 10
// speedup vs baseline: 3.8477x; 1.0072x over previous
#include <cuda_runtime.h>
#include <cuda_fp16.h>
#include <math.h>
#include <stdint.h>

// ---------------- problem constants ----------------
#define BATCH    2
#define LQ       21760
#define LEN_IN   21760
#define DMODEL   256
#define NHEADS   8
#define HDIM     32
#define MROWS    (BATCH*LQ)       // 43520
#define NQP      384              // fused off(256)+attn(128)
#define KDIM     256
#define GPB      32               // (q,h) pairs per sampler block
#define PGRID    296              // persistent GEMM grid (2 CTAs x 148 SMs)

// level geometry
__device__ __constant__ int c_lvlWH[4]   = {128, 64, 32, 16};
__device__ __constant__ int c_lvlBase[4] = {0, 16384, 20480, 21504};

// ---------------- scratch ----------------
__device__ __align__(16) __half g_value_h[(size_t)BATCH*NHEADS*LEN_IN*HDIM]; // [b][h][pix][32]
__device__ float g_qproj[(size_t)MROWS*NQP];
__device__ __align__(16) __half g_samp_h[(size_t)MROWS*DMODEL];
// weights in [k][n] layout
__device__ __half g_Wq_hi[KDIM*NQP];                       // qproj: 1-pass
__device__ __half g_Wv_hi[KDIM*DMODEL];                    // value: 1-pass
__device__ __half g_Wo_hi[KDIM*DMODEL], g_Wo_lo[KDIM*DMODEL];  // out: 2-pass
__device__ float g_bq[NQP];

// ---------------- PTX helpers ----------------
__device__ __forceinline__ uint32_t smem_u32(const void* p) {
    uint32_t a;
    asm("{ .reg .u64 t; cvta.to.shared.u64 t, %1; cvt.u32.u64 %0, t; }" : "=r"(a) : "l"(p));
    return a;
}
__device__ __forceinline__ void ldsm4(uint32_t* r, uint32_t a) {
    asm volatile("ldmatrix.sync.aligned.m8n8.x4.shared.b16 {%0,%1,%2,%3}, [%4];"
                 : "=r"(r[0]), "=r"(r[1]), "=r"(r[2]), "=r"(r[3]) : "r"(a));
}
__device__ __forceinline__ void ldsm4t(uint32_t* r, uint32_t a) {
    asm volatile("ldmatrix.sync.aligned.m8n8.x4.trans.shared.b16 {%0,%1,%2,%3}, [%4];"
                 : "=r"(r[0]), "=r"(r[1]), "=r"(r[2]), "=r"(r[3]) : "r"(a));
}
__device__ __forceinline__ void mma16816(float* c, const uint32_t* a, const uint32_t* b) {
    asm volatile("mma.sync.aligned.m16n8k16.row.col.f32.f16.f16.f32 "
                 "{%0,%1,%2,%3}, {%4,%5,%6,%7}, {%8,%9}, {%0,%1,%2,%3};"
                 : "+f"(c[0]), "+f"(c[1]), "+f"(c[2]), "+f"(c[3])
                 : "r"(a[0]), "r"(a[1]), "r"(a[2]), "r"(a[3]), "r"(b[0]), "r"(b[1]));
}
__device__ __forceinline__ void cpa16(uint32_t s, const void* g) {
    asm volatile("cp.async.cg.shared.global [%0], [%1], 16;" :: "r"(s), "l"(g));
}
__device__ __forceinline__ uint32_t packh(__half a, __half b) {
    __half2 t = __halves2half2(a, b);
    return *(uint32_t*)&t;
}

// ---------------- weight prep ----------------
__global__ void prep_weights(const float* __restrict__ W_off, const float* __restrict__ b_off,
                             const float* __restrict__ W_attn, const float* __restrict__ b_attn,
                             const float* __restrict__ W_val, const float* __restrict__ W_out)
{
    const int i = blockIdx.x * 256 + threadIdx.x;
    const int NQ = KDIM * NQP;
    const int NV = KDIM * DMODEL;
    if (i < NQ) {
        int k = i / NQP, n = i % NQP;
        float w = (n < 256) ? W_off[k * 256 + n] : W_attn[k * 128 + (n - 256)];
        g_Wq_hi[i] = __float2half_rn(w);
    } else if (i < NQ + NV) {
        int idx = i - NQ;
        g_Wv_hi[idx] = __float2half_rn(W_val[idx]);
    } else if (i < NQ + 2 * NV) {
        int idx = i - NQ - NV;
        float w = W_out[idx];
        __half hi = __float2half_rn(w);
        g_Wo_hi[idx] = hi;
        g_Wo_lo[idx] = __float2half_rn(w - __half2float(hi));
    } else return;
    if (i < NQP) g_bq[i] = (i < 256) ? b_off[i] : b_attn[i - 256];
}

// ---------------- HMMA GEMM (persistent CTAs) ----------------
// AMODE 0: A fp32, converted to fp16 in loader.  AMODE 1: A fp16, cp.async.
// BLO: add the W_lo correction pass.  VOUT: fp16 head-major value epilogue.
#define ASTRIDE 144
#define BSTRIDE 272
#define SOFF_BH 18432
#define SOFF_BL (18432+17408)
#define STAGE   (18432+2*17408)       // 53248
#define SMEM_GEMM (2*STAGE)           // 106496

template<int AMODE, bool BLO, bool VOUT>
__global__ __launch_bounds__(256, 2)
void gemm_hmma(const void* __restrict__ Aptr,
               const __half* __restrict__ Wh, const __half* __restrict__ Wl,
               const float* __restrict__ bias, float* __restrict__ C,
               int N, int ntiles, int nx)
{
    extern __shared__ __align__(16) char dsm[];
    const uint32_t sb = smem_u32(dsm);

    const int tid  = threadIdx.x;
    const int wid  = tid >> 5;
    const int lane = tid & 31;
    const int m0   = (wid & 3) * 32;
    const int n0w  = (wid >> 2) * 64;

    const uint32_t aOff = (uint32_t)((m0 + (lane & 15)) * ASTRIDE + (lane >> 4) * 16);
    const uint32_t bOff = (uint32_t)(((lane & 7) + ((lane >> 3) & 1) * 8) * BSTRIDE
                                     + (lane >> 4) * 16 + n0w * 2);

    for (int t = blockIdx.x; t < ntiles; t += gridDim.x) {
        const int bm = (t / nx) * 128;
        const int bn = (t % nx) * 128;

        float acc[2][8][4];
        #pragma unroll
        for (int i = 0; i < 2; i++)
            #pragma unroll
            for (int j = 0; j < 8; j++)
                #pragma unroll
                for (int q = 0; q < 4; q++) acc[i][j][q] = 0.f;

        auto loadA = [&](int c, int buf) {
            const uint32_t st = sb + buf * STAGE;
            if (AMODE == 1) {
                const __half* Ah = (const __half*)Aptr;
                #pragma unroll
                for (int it = 0; it < 4; it++) {
                    int idx = tid + it * 256;
                    int r   = idx >> 3;
                    int col = (idx & 7) * 8;
                    cpa16(st + r * ASTRIDE + col * 2,
                          Ah + (size_t)(bm + r) * KDIM + c * 64 + col);
                }
            } else {
                const float* Af = (const float*)Aptr;
                #pragma unroll
                for (int it = 0; it < 8; it++) {
                    int idx = tid + it * 256;
                    int r   = idx >> 4;
                    int k4  = (idx & 15) * 4;
                    float4 a = *(const float4*)(Af + (size_t)(bm + r) * KDIM + c * 64 + k4);
                    uint32_t h01 = packh(__float2half_rn(a.x), __float2half_rn(a.y));
                    uint32_t h23 = packh(__float2half_rn(a.z), __float2half_rn(a.w));
                    asm volatile("st.shared.v2.b32 [%0], {%1, %2};"
                                 :: "r"(st + r * ASTRIDE + k4 * 2), "r"(h01), "r"(h23) : "memory");
                }
            }
        };
        auto issueB = [&](int c, int buf) {
            const uint32_t st = sb + buf * STAGE;
            const int nit = BLO ? 8 : 4;
            for (int it = 0; it < nit; it++) {
                int idx = tid + it * 256;
                const __half* src = (it < 4) ? Wh : Wl;
                const uint32_t mo = (it < 4) ? 0u : (uint32_t)(SOFF_BL - SOFF_BH);
                int j   = idx & 1023;
                int r   = j >> 4;
                int col = (j & 15) * 8;
                cpa16(st + SOFF_BH + mo + r * BSTRIDE + col * 2,
                      src + (size_t)(c * 64 + r) * N + bn + col);
            }
        };

        // prologue
        loadA(0, 0);
        issueB(0, 0);
        asm volatile("cp.async.commit_group;" ::: "memory");

        for (int c = 0; c < 4; c++) {
            if (c < 3) {
                loadA(c + 1, (c + 1) & 1);
                issueB(c + 1, (c + 1) & 1);
                asm volatile("cp.async.commit_group;" ::: "memory");
                asm volatile("cp.async.wait_group 1;" ::: "memory");
            } else {
                asm volatile("cp.async.wait_group 0;" ::: "memory");
            }
            __syncthreads();

            const uint32_t st = sb + (c & 1) * STAGE;
            #pragma unroll
            for (int ks = 0; ks < 4; ks++) {
                uint32_t ah[2][4];
                ldsm4(ah[0], st + aOff + ks * 32);
                ldsm4(ah[1], st + aOff + 16 * ASTRIDE + ks * 32);
                #pragma unroll
                for (int hh = 0; hh < 2; hh++) {
                    const uint32_t bks = bOff + ks * (16 * BSTRIDE) + hh * 64;
                    uint32_t bh[8];
                    ldsm4t(bh,     st + SOFF_BH + bks);
                    ldsm4t(bh + 4, st + SOFF_BH + bks + 32);
                    #pragma unroll
                    for (int j = 0; j < 4; j++)
                        #pragma unroll
                        for (int i = 0; i < 2; i++)
                            mma16816(acc[i][hh * 4 + j], ah[i], bh + j * 2);
                    if (BLO) {
                        uint32_t bl[8];
                        ldsm4t(bl,     st + SOFF_BL + bks);
                        ldsm4t(bl + 4, st + SOFF_BL + bks + 32);
                        #pragma unroll
                        for (int j = 0; j < 4; j++)
                            #pragma unroll
                            for (int i = 0; i < 2; i++)
                                mma16816(acc[i][hh * 4 + j], ah[i], bl + j * 2);
                    }
                }
            }
            __syncthreads();
        }

        // ---- epilogue ----
        if (VOUT) {
            const int bb = (bm >= LEN_IN) ? 1 : 0;
            const int pixbase = bm - bb * LEN_IN;
            #pragma unroll
            for (int i = 0; i < 2; i++) {
                const int pix = pixbase + m0 + i * 16 + (lane >> 2);
                #pragma unroll
                for (int j = 0; j < 8; j++) {
                    const int cc = bn + n0w + j * 8 + (lane & 3) * 2;
                    const int head = cc >> 5, chp = cc & 31;
                    const float2 bv = *(const float2*)(bias + cc);
                    __half* dst = g_value_h
                        + ((size_t)(bb * NHEADS + head) * LEN_IN + pix) * HDIM + chp;
                    __half2 v0 = __floats2half2_rn(acc[i][j][0] + bv.x, acc[i][j][1] + bv.y);
                    __half2 v1 = __floats2half2_rn(acc[i][j][2] + bv.x, acc[i][j][3] + bv.y);
                    *(__half2*)dst = v0;
                    *(__half2*)(dst + 8 * HDIM) = v1;
                }
            }
        } else {
            #pragma unroll
            for (int i = 0; i < 2; i++) {
                const int r0 = bm + m0 + i * 16 + (lane >> 2);
                #pragma unroll
                for (int j = 0; j < 8; j++) {
                    const int cc = bn + n0w + j * 8 + (lane & 3) * 2;
                    const float2 bv = *(const float2*)(bias + cc);
                    float2 v0 = make_float2(acc[i][j][0] + bv.x, acc[i][j][1] + bv.y);
                    float2 v1 = make_float2(acc[i][j][2] + bv.x, acc[i][j][3] + bv.y);
                    *(float2*)(C + (size_t)r0 * N + cc) = v0;
                    *(float2*)(C + (size_t)(r0 + 8) * N + cc) = v1;
                }
            }
        }
    }
}

// ---------------- block-staged softmax + deformable sampling ----------------
__global__ __launch_bounds__(256)
void deform_sample(const float* __restrict__ refp)
{
    __shared__ uint4 s_pw[GPB][32];

    const int tid = threadIdx.x;

    // ---------- phase 1 ----------
    {
        const int pi  = tid >> 3;
        const int sub = tid & 7;
        const int gp  = blockIdx.x * GPB + pi;
        const int h   = gp & 7;
        const int bq  = gp >> 3;
        const float* row = g_qproj + (size_t)bq * NQP;

        float lg0 = row[256 + h * 16 + 2 * sub];
        float lg1 = row[256 + h * 16 + 2 * sub + 1];
        float mx = fmaxf(lg0, lg1);
        #pragma unroll
        for (int s = 1; s < 8; s <<= 1) mx = fmaxf(mx, __shfl_xor_sync(0xffffffffu, mx, s));
        float e0 = __expf(lg0 - mx), e1 = __expf(lg1 - mx);
        float sm = e0 + e1;
        #pragma unroll
        for (int s = 1; s < 8; s <<= 1) sm += __shfl_xor_sync(0xffffffffu, sm, s);
        const float inv = __frcp_rn(sm);

        const float4 of = *(const float4*)(row + h * 32 + sub * 4);
        const int l = sub >> 1;
        const float2 rf = *(const float2*)(refp + (size_t)bq * 8 + l * 2);

        const int   WH   = c_lvlWH[l];
        const int   base = c_lvlBase[l];
        const float Wf   = (float)WH;

        #pragma unroll
        for (int pp = 0; pp < 2; pp++) {
            const float ox = pp ? of.z : of.x;
            const float oy = pp ? of.w : of.y;
            const float wat = (pp ? e1 : e0) * inv;

            const float ix = fmaf(rf.x, Wf, ox) - 0.5f;
            const float iy = fmaf(rf.y, Wf, oy) - 0.5f;
            const float x0f = floorf(ix), y0f = floorf(iy);
            const int   x0 = (int)x0f,    y0 = (int)y0f;
            const float fx = ix - x0f,    fy = iy - y0f;

            const int x1 = x0 + 1, y1 = y0 + 1;
            const float vx0 = (x0 >= 0 && x0 < WH) ? 1.f : 0.f;
            const float vx1 = (x1 >= 0 && x1 < WH) ? 1.f : 0.f;
            const float vy0 = (y0 >= 0 && y0 < WH) ? 1.f : 0.f;
            const float vy1 = (y1 >= 0 && y1 < WH) ? 1.f : 0.f;

            const int cx0 = min(max(x0, 0), WH - 1);
            const int cx1 = min(max(x1, 0), WH - 1);
            const int cy0 = min(max(y0, 0), WH - 1);
            const int cy1 = min(max(y1, 0), WH - 1);

            const int p = sub * 2 + pp;
            s_pw[pi][p * 2 + 0] = make_uint4(
                (uint32_t)(base + cy0 * WH + cx0) << 6,
                __float_as_uint((1.f - fx) * (1.f - fy) * vy0 * vx0 * wat),
                (uint32_t)(base + cy0 * WH + cx1) << 6,
                __float_as_uint(fx * (1.f - fy) * vy0 * vx1 * wat));
            s_pw[pi][p * 2 + 1] = make_uint4(
                (uint32_t)(base + cy1 * WH + cx0) << 6,
                __float_as_uint((1.f - fx) * fy * vy1 * vx0 * wat),
                (uint32_t)(base + cy1 * WH + cx1) << 6,
                __float_as_uint(fx * fy * vy1 * vx1 * wat));
        }
    }
    __syncthreads();

    // ---------- phase 2 ----------
    const int wid  = tid >> 5;
    const int lane = tid & 31;
    const int g    = lane >> 2;
    const int quad = lane & 3;

    #pragma unroll 1
    for (int pp = 0; pp < 4; pp++) {
        const int pi = wid * 4 + pp;
        const int gp = blockIdx.x * GPB + pi;
        const int h  = gp & 7;
        const int bq = gp >> 3;
        const int b  = (bq >= LQ) ? 1 : 0;
        const char* vbc = (const char*)g_value_h
            + ((size_t)(b * NHEADS + h) * LEN_IN) * (HDIM * 2) + quad * 16;
        const char* pwb = (const char*)&s_pw[pi][0] + g * 8;

        float a0 = 0.f, a1 = 0.f, a2 = 0.f, a3 = 0.f, a4 = 0.f, a5 = 0.f, a6 = 0.f, a7 = 0.f;
        #pragma unroll
        for (int t = 0; t < 8; t++) {
            const uint2 pw = *(const uint2*)(pwb + t * 64);
            const float w  = __uint_as_float(pw.y);
            const uint4 v  = *(const uint4*)(vbc + pw.x);
            const float2 f0 = __half22float2(*(const __half2*)&v.x);
            const float2 f1 = __half22float2(*(const __half2*)&v.y);
            const float2 f2 = __half22float2(*(const __half2*)&v.z);
            const float2 f3 = __half22float2(*(const __half2*)&v.w);
            a0 = fmaf(w, f0.x, a0); a1 = fmaf(w, f0.y, a1);
            a2 = fmaf(w, f1.x, a2); a3 = fmaf(w, f1.y, a3);
            a4 = fmaf(w, f2.x, a4); a5 = fmaf(w, f2.y, a5);
            a6 = fmaf(w, f3.x, a6); a7 = fmaf(w, f3.y, a7);
        }
        #pragma unroll
        for (int s = 4; s <= 16; s <<= 1) {
            a0 += __shfl_xor_sync(0xffffffffu, a0, s);
            a1 += __shfl_xor_sync(0xffffffffu, a1, s);
            a2 += __shfl_xor_sync(0xffffffffu, a2, s);
            a3 += __shfl_xor_sync(0xffffffffu, a3, s);
            a4 += __shfl_xor_sync(0xffffffffu, a4, s);
            a5 += __shfl_xor_sync(0xffffffffu, a5, s);
            a6 += __shfl_xor_sync(0xffffffffu, a6, s);
            a7 += __shfl_xor_sync(0xffffffffu, a7, s);
        }
        if (lane < 4) {
            __half2 h0 = __floats2half2_rn(a0, a1);
            __half2 h1 = __floats2half2_rn(a2, a3);
            __half2 h2 = __floats2half2_rn(a4, a5);
            __half2 h3 = __floats2half2_rn(a6, a7);
            uint4 st = make_uint4(*(uint32_t*)&h0, *(uint32_t*)&h1,
                                  *(uint32_t*)&h2, *(uint32_t*)&h3);
            *(uint4*)((char*)g_samp_h + (size_t)bq * (DMODEL * 2) + h * 64 + lane * 16) = st;
        }
    }
}

// ---------------- launch ----------------
extern "C" void kernel_launch(void* const* d_in, const int* in_sizes, int n_in,
                              void* d_out, int out_size)
{
    (void)in_sizes; (void)n_in; (void)out_size;
    const float* query  = (const float*)d_in[0];
    const float* refp   = (const float*)d_in[1];
    const float* xin    = (const float*)d_in[2];
    const float* W_off  = (const float*)d_in[3];
    const float* b_off  = (const float*)d_in[4];
    const float* W_attn = (const float*)d_in[5];
    const float* b_attn = (const float*)d_in[6];
    const float* W_val  = (const float*)d_in[7];
    const float* b_val  = (const float*)d_in[8];
    const float* W_out  = (const float*)d_in[9];
    const float* b_out  = (const float*)d_in[10];
    float* out = (float*)d_out;

    float *p_qproj, *p_bq;
    __half *p_samp_h, *p_Wq_hi, *p_Wv_hi, *p_Wo_hi, *p_Wo_lo;
    cudaGetSymbolAddress((void**)&p_qproj,  g_qproj);
    cudaGetSymbolAddress((void**)&p_samp_h, g_samp_h);
    cudaGetSymbolAddress((void**)&p_bq,     g_bq);
    cudaGetSymbolAddress((void**)&p_Wq_hi,  g_Wq_hi);
    cudaGetSymbolAddress((void**)&p_Wv_hi,  g_Wv_hi);
    cudaGetSymbolAddress((void**)&p_Wo_hi,  g_Wo_hi);
    cudaGetSymbolAddress((void**)&p_Wo_lo,  g_Wo_lo);

    cudaFuncSetAttribute(gemm_hmma<0, false, true>,  cudaFuncAttributeMaxDynamicSharedMemorySize, SMEM_GEMM);
    cudaFuncSetAttribute(gemm_hmma<0, false, false>, cudaFuncAttributeMaxDynamicSharedMemorySize, SMEM_GEMM);
    cudaFuncSetAttribute(gemm_hmma<1, true,  false>, cudaFuncAttributeMaxDynamicSharedMemorySize, SMEM_GEMM);

    // 0) weight prep
    {
        const int total = KDIM * NQP + 2 * KDIM * DMODEL;
        prep_weights<<<(total + 255) / 256, 256>>>(W_off, b_off, W_attn, b_attn, W_val, W_out);
    }

    const int MB = MROWS / 128;   // 340

    // 1) value projection: fp32 A (inline cvt), 1-pass, fp16 head-major out
    gemm_hmma<0, false, true><<<PGRID, 256, SMEM_GEMM>>>(
        xin, p_Wv_hi, nullptr, b_val, nullptr, 256, 2 * MB, 2);

    // 2) fused query projection (N=384): fp32 A, 1-pass
    gemm_hmma<0, false, false><<<PGRID, 256, SMEM_GEMM>>>(
        query, p_Wq_hi, nullptr, p_bq, p_qproj, NQP, 3 * MB, 3);

    // 3) block-staged softmax + deformable sampling -> fp16 samp
    deform_sample<<<(MROWS * NHEADS) / GPB, 256>>>(refp);

    // 4) output projection: fp16 A (exact), 2-pass
    gemm_hmma<1, true, false><<<PGRID, 256, SMEM_GEMM>>>(
        p_samp_h, p_Wo_hi, p_Wo_lo, b_out, out, 256, 2 * MB, 2);
}